// round 6
// baseline (speedup 1.0000x reference)
#include <cuda_runtime.h>
#include <cuda_bf16.h>
#include <math.h>
#include <cstdint>

// ---------------------------------------------------------------------------
// Problem constants: B=2, L=2048, D=2048, H=16, dk=64, dv=128.  M = B*L = 4096.
// ---------------------------------------------------------------------------
#define MTOK 4096
#define DMODEL 2048
#define DQK 1024
#define NHEAD 16
#define DK 64
#define DV 128
#define SEQ 2048
#define SCALE_K 0.08838834764831845f   // 128^-0.5
#define INV_NORM 0.0625f               // 1/16

// tcgen05 only exists in the arch-specific (sm_103a) compilation pass.
#if defined(__CUDA_ARCH__) && (__CUDA_ARCH__ == 1030) && defined(__CUDA_ARCH_FEAT_SM103_ALL)
#define USE_TCGEN05 1
#else
#define USE_TCGEN05 0
#endif

// ---------------------------------------------------------------------------
// Scratch (device globals: no allocation allowed)
// ---------------------------------------------------------------------------
__device__ float g_q [MTOK * DQK];
__device__ float g_k [MTOK * DQK];
__device__ float g_kg[MTOK * DQK];
__device__ float g_v [MTOK * DMODEL];
__device__ float g_gp[MTOK * DMODEL];
__device__ float g_o [MTOK * DMODEL];
__device__ float g_t16[MTOK * 16];

__device__ __nv_bfloat16 g_xh[MTOK * DMODEL],   g_xl[MTOK * DMODEL];
__device__ __nv_bfloat16 g_zh[MTOK * DMODEL],   g_zl[MTOK * DMODEL];
__device__ __nv_bfloat16 g_wqh[DQK * DMODEL],   g_wql[DQK * DMODEL];
__device__ __nv_bfloat16 g_wkh[DQK * DMODEL],   g_wkl[DQK * DMODEL];
__device__ __nv_bfloat16 g_wvh[DMODEL * DMODEL], g_wvl[DMODEL * DMODEL];
__device__ __nv_bfloat16 g_wgh[DMODEL * DMODEL], g_wgl[DMODEL * DMODEL];
__device__ __nv_bfloat16 g_woh[DMODEL * DMODEL], g_wol[DMODEL * DMODEL];

// ---------------------------------------------------------------------------
// PTX helpers
// ---------------------------------------------------------------------------
__device__ __forceinline__ uint32_t smem_u32(const void* p) {
    uint32_t a;
    asm("{ .reg .u64 t; cvta.to.shared.u64 t, %1; cvt.u32.u64 %0, t; }" : "=r"(a) : "l"(p));
    return a;
}

#define SWZ(o) ((o) ^ (((o) >> 3) & 0x70))

#define CP_ASYNC16(dst, src) \
    asm volatile("cp.async.cg.shared.global [%0], [%1], 16;" :: "r"(dst), "l"(src))
#define CP_ASYNC_COMMIT() \
    asm volatile("cp.async.commit_group;" ::: "memory")
#define CP_ASYNC_WAIT(n) \
    asm volatile("cp.async.wait_group %0;" :: "n"(n) : "memory")

#if USE_TCGEN05
__device__ __forceinline__ uint32_t elect_one_pred() {
    uint32_t pred;
    asm volatile("{\n\t.reg .pred p;\n\telect.sync _|p, 0xFFFFFFFF;\n\t"
                 "selp.b32 %0, 1, 0, p;\n\t}" : "=r"(pred));
    return pred;
}

#define MBARRIER_INIT(mb, cnt) \
    asm volatile("mbarrier.init.shared.b64 [%0], %1;" :: "r"((uint32_t)(mb)), "r"((uint32_t)(cnt)) : "memory")

#define MBARRIER_WAIT_PARITY(mb, par) do { \
    uint32_t _mb = (uint32_t)(mb); uint32_t _p = (uint32_t)(par); uint32_t _done; \
    asm volatile("{\n\t.reg .pred p;\n\t" \
        "mbarrier.try_wait.parity.acquire.cta.shared::cta.b64 p, [%1], %2;\n\t" \
        "selp.b32 %0, 1, 0, p;\n\t}" : "=r"(_done) : "r"(_mb), "r"(_p) : "memory"); \
    if (!_done) { \
        asm volatile("{\n\t.reg .pred P1;\n\t" \
            "WL_%=:\n\t" \
            "mbarrier.try_wait.parity.acquire.cta.shared::cta.b64 P1, [%0], %1, 0x989680;\n\t" \
            "@P1 bra.uni WD_%=;\n\t" \
            "bra.uni WL_%=;\n\t" \
            "WD_%=:\n\t}" :: "r"(_mb), "r"(_p) : "memory"); \
    } \
} while (0)

#define TCGEN05_ALLOC(smem_res, ncols) \
    asm volatile("tcgen05.alloc.cta_group::1.sync.aligned.shared::cta.b32 [%0], %1;" \
                 :: "r"((uint32_t)(smem_res)), "r"((uint32_t)(ncols)) : "memory")
#define TCGEN05_DEALLOC(tm, ncols) \
    asm volatile("tcgen05.dealloc.cta_group::1.sync.aligned.b32 %0, %1;" :: "r"(tm), "r"((uint32_t)(ncols)))
#define TCGEN05_RELINQ() \
    asm volatile("tcgen05.relinquish_alloc_permit.cta_group::1.sync.aligned;")
#define TCGEN05_COMMIT(mb) \
    asm volatile("tcgen05.commit.cta_group::1.mbarrier::arrive::one.shared::cluster.b64 [%0];" \
                 :: "r"((uint32_t)(mb)) : "memory")
#define TCGEN05_FENCE_AFTER() \
    asm volatile("tcgen05.fence::after_thread_sync;" ::: "memory")
#define TCGEN05_WAIT_LD() \
    asm volatile("tcgen05.wait::ld.sync.aligned;" ::: "memory")
#define FENCE_PROXY_ASYNC() \
    asm volatile("fence.proxy.async.shared::cta;" ::: "memory")

#define TCGEN05_LD_X32(r, tm) \
    asm volatile("tcgen05.ld.sync.aligned.32x32b.x32.b32 " \
        "{%0, %1, %2, %3, %4, %5, %6, %7, %8, %9, %10, %11, %12, %13, %14, %15, " \
        " %16, %17, %18, %19, %20, %21, %22, %23, %24, %25, %26, %27, %28, %29, %30, %31}, [%32];" \
        : "=r"((r)[0]),  "=r"((r)[1]),  "=r"((r)[2]),  "=r"((r)[3]), \
          "=r"((r)[4]),  "=r"((r)[5]),  "=r"((r)[6]),  "=r"((r)[7]), \
          "=r"((r)[8]),  "=r"((r)[9]),  "=r"((r)[10]), "=r"((r)[11]), \
          "=r"((r)[12]), "=r"((r)[13]), "=r"((r)[14]), "=r"((r)[15]), \
          "=r"((r)[16]), "=r"((r)[17]), "=r"((r)[18]), "=r"((r)[19]), \
          "=r"((r)[20]), "=r"((r)[21]), "=r"((r)[22]), "=r"((r)[23]), \
          "=r"((r)[24]), "=r"((r)[25]), "=r"((r)[26]), "=r"((r)[27]), \
          "=r"((r)[28]), "=r"((r)[29]), "=r"((r)[30]), "=r"((r)[31]) \
        : "r"(tm))

// K-major SW128 descriptor: layout=2 (SW128), version=1, SBO=64, LBO=1
static constexpr uint64_t DESC_BASE_SW128 =
    (uint64_t(2) << 61) | (uint64_t(1) << 46) | (uint64_t(64) << 32) | (uint64_t(1) << 16);
#define MAKE_DESC(addr) (DESC_BASE_SW128 | ((uint64_t)((addr) >> 4) & 0x3FFF))

__device__ __forceinline__ void mma_f16_ss(uint32_t d, uint64_t ad, uint64_t bd,
                                           uint32_t idesc, uint32_t en) {
    asm volatile("{\n\t.reg .pred p;\n\tsetp.ne.u32 p, %5, 0;\n\t"
        "tcgen05.mma.cta_group::1.kind::f16 [%0], %1, %2, %3, {%4, %4, %4, %4}, p;\n\t}"
        :: "r"(d), "l"(ad), "l"(bd), "r"(idesc), "r"(0u), "r"(en) : "memory");
}
#else
// HMMA fallback primitive: m16n8k16 row.col bf16 -> f32
__device__ __forceinline__ void mma16816(float* d, const uint32_t* a, const uint32_t* b) {
    asm volatile("mma.sync.aligned.m16n8k16.row.col.f32.bf16.bf16.f32 "
        "{%0,%1,%2,%3}, {%4,%5,%6,%7}, {%8,%9}, {%0,%1,%2,%3};"
        : "+f"(d[0]), "+f"(d[1]), "+f"(d[2]), "+f"(d[3])
        : "r"(a[0]), "r"(a[1]), "r"(a[2]), "r"(a[3]), "r"(b[0]), "r"(b[1]));
}
#endif

// ---------------------------------------------------------------------------
// bf16x3 GEMM:  C[M,N] = alpha * (A @ B^T) (+ bias), split hi/lo operands.
// Tile 128x256 (two N=128 MMA halves), K-chunk 64, 256 threads,
// double-buffered swizzled SMEM, cp.async loads, MMA-issue-first pipeline.
// Buffer layout: Ah 16K | Al 16K | Bh 32K | Bl 32K  = 96KB per stage.
// ---------------------------------------------------------------------------
#define BUFB 98304
#define GEMM_DSM (2 * BUFB + 1024)

__global__ __launch_bounds__(256) __cluster_dims__(1, 1, 1)
void gemm3(const __nv_bfloat16* __restrict__ Ah, const __nv_bfloat16* __restrict__ Al,
           const __nv_bfloat16* __restrict__ Bh, const __nv_bfloat16* __restrict__ Bl,
           const float* __restrict__ bias, float* __restrict__ C,
           int N, int K, float alpha)
{
    extern __shared__ char dsm[];

    const int tid = threadIdx.x;
    const int bm = blockIdx.y * 128;
    const int bn = blockIdx.x * 256;

    const uint32_t raw = smem_u32(dsm);
    const uint32_t sbase = (raw + 1023u) & ~1023u;
    char* sgen = dsm + (sbase - raw);

    // async chunk loader. A tiles 128 rows, B tiles 256 rows; rows x 128B, SW128.
    const int lr  = tid >> 3;          // 0..31 base row (stride 32)
    const int seg = tid & 7;           // 16B segment within 128B row
    auto load_chunk = [&](int c) {
        uint32_t bb = sbase + (c & 1) * BUFB;
        const int k0 = c * 64;
#pragma unroll
        for (int t2 = 0; t2 < 2; t2++) {               // Ah, Al
            const __nv_bfloat16* basep = t2 ? Al : Ah;
            uint32_t tb = bb + t2 * 16384;
#pragma unroll
            for (int ii = 0; ii < 4; ii++) {
                int r = lr + ii * 32;
                const void* src = basep + (size_t)(bm + r) * K + k0 + seg * 8;
                CP_ASYNC16(tb + SWZ((uint32_t)(r * 128 + seg * 16)), src);
            }
        }
#pragma unroll
        for (int t2 = 0; t2 < 2; t2++) {               // Bh, Bl (256 rows)
            const __nv_bfloat16* basep = t2 ? Bl : Bh;
            uint32_t tb = bb + 32768 + t2 * 32768;
#pragma unroll
            for (int ii = 0; ii < 8; ii++) {
                int r = lr + ii * 32;
                const void* src = basep + (size_t)(bn + r) * K + k0 + seg * 8;
                CP_ASYNC16(tb + SWZ((uint32_t)(r * 128 + seg * 16)), src);
            }
        }
        CP_ASYNC_COMMIT();
    };

    const int NC = K / 64;

#if USE_TCGEN05
    __shared__ uint32_t s_tmem;
    __shared__ __align__(16) uint64_t s_mbar[2];   // one per SMEM buffer
    const uint32_t mbar0 = smem_u32(&s_mbar[0]);
    const uint32_t mbar1 = smem_u32(&s_mbar[1]);

    if (tid < 32) { TCGEN05_ALLOC(smem_u32(&s_tmem), 256); TCGEN05_RELINQ(); }
    if (tid == 0) { MBARRIER_INIT(mbar0, 1); MBARRIER_INIT(mbar1, 1); }
    __syncthreads();
    const uint32_t tmem = s_tmem;

    const uint32_t IDESC = (1u << 4) | (1u << 7) | (1u << 10) | (16u << 17) | (8u << 24);

    load_chunk(0);

    for (int c = 0; c < NC; c++) {
        CP_ASYNC_WAIT(0);              // chunk c resident
        FENCE_PROXY_ASYNC();
        __syncthreads();

        if (tid < 32 && elect_one_pred()) {
            const uint32_t ab = sbase + (c & 1) * BUFB;
            const uint64_t dAh  = MAKE_DESC(ab);
            const uint64_t dAl  = MAKE_DESC(ab + 16384);
            const uint64_t dBh0 = MAKE_DESC(ab + 32768);
            const uint64_t dBh1 = MAKE_DESC(ab + 32768 + 16384);
            const uint64_t dBl0 = MAKE_DESC(ab + 65536);
            const uint64_t dBl1 = MAKE_DESC(ab + 65536 + 16384);
            const uint32_t en0 = (c > 0);
#pragma unroll
            for (int ks = 0; ks < 4; ks++)
                mma_f16_ss(tmem,       dAh + ks * 2, dBh0 + ks * 2, IDESC, en0 || (ks > 0));
#pragma unroll
            for (int ks = 0; ks < 4; ks++)
                mma_f16_ss(tmem + 128, dAh + ks * 2, dBh1 + ks * 2, IDESC, en0 || (ks > 0));
#pragma unroll
            for (int ks = 0; ks < 4; ks++) {
                mma_f16_ss(tmem,       dAh + ks * 2, dBl0 + ks * 2, IDESC, 1u);
                mma_f16_ss(tmem + 128, dAh + ks * 2, dBl1 + ks * 2, IDESC, 1u);
                mma_f16_ss(tmem,       dAl + ks * 2, dBh0 + ks * 2, IDESC, 1u);
                mma_f16_ss(tmem + 128, dAl + ks * 2, dBh1 + ks * 2, IDESC, 1u);
            }
            TCGEN05_COMMIT((c & 1) ? mbar1 : mbar0);
        }

        if (c + 1 < NC) {
            if (c >= 1) {
                // buffer (c+1)&1 was used by MMA chunk c-1; wait for it.
                MBARRIER_WAIT_PARITY(((c - 1) & 1) ? mbar1 : mbar0, ((c - 1) >> 1) & 1);
            }
            load_chunk(c + 1);
        }
    }
    MBARRIER_WAIT_PARITY(((NC - 1) & 1) ? mbar1 : mbar0, ((NC - 1) >> 1) & 1);
    TCGEN05_FENCE_AFTER();
    __syncthreads();

    // epilogue: TMEM -> regs -> padded SMEM stage -> coalesced STG (8 slabs)
    float* stage = (float*)sgen;
    for (int slab = 0; slab < 8; slab++) {
        if (tid < 128) {
            uint32_t regs[32];
            TCGEN05_LD_X32(regs, tmem + slab * 32);
            TCGEN05_WAIT_LD();
#pragma unroll
            for (int cc = 0; cc < 32; cc++) stage[tid * 33 + cc] = __uint_as_float(regs[cc]);
        }
        __syncthreads();
#pragma unroll
        for (int i = 0; i < 16; i++) {
            int e = i * 256 + tid;
            int row = e >> 5, col = e & 31;
            float vv = stage[row * 33 + col] * alpha;
            if (bias) vv += bias[bn + slab * 32 + col];
            C[(size_t)(bm + row) * N + bn + slab * 32 + col] = vv;
        }
        __syncthreads();
    }
    if (tid < 32) TCGEN05_DEALLOC(tmem, 256);

#else  // ------------------- HMMA mma.sync fallback ------------------------
    // Two passes over the N halves (re-loads A/B; fallback only, never selected
    // on sm_103a hardware — kept for the non-arch-specific compile pass).
    const int warp = tid >> 5;
    const int lane = tid & 31;
    const int wm = (warp & 3) * 32;     // warp tile 32 x 64
    const int wn = (warp >> 2) * 64;
    const int lg = lane >> 2;           // 0..7
    const int lt = lane & 3;            // 0..3

    for (int nh = 0; nh < 2; nh++) {
        float acc[2][8][4];
#pragma unroll
        for (int mt = 0; mt < 2; mt++)
#pragma unroll
            for (int nt = 0; nt < 8; nt++)
#pragma unroll
                for (int r = 0; r < 4; r++) acc[mt][nt][r] = 0.f;

        load_chunk(0);

        for (int c = 0; c < NC; c++) {
            if (c + 1 < NC) { load_chunk(c + 1); CP_ASYNC_WAIT(1); }
            else            { CP_ASYNC_WAIT(0); }
            __syncthreads();

            char* bb = sgen + (c & 1) * BUFB;
            char* tAh = bb, *tAl = bb + 16384;
            char* tBh = bb + 32768 + nh * 16384, *tBl = bb + 65536 + nh * 16384;

#pragma unroll
            for (int kk = 0; kk < 64; kk += 16) {
                const uint32_t kbase = (kk + lt * 2) * 2;
                uint32_t bh[8][2], bl[8][2];
#pragma unroll
                for (int nt = 0; nt < 8; nt++) {
                    uint32_t off = (uint32_t)((wn + nt * 8 + lg) * 128) + kbase;
                    bh[nt][0] = *(const uint32_t*)(tBh + SWZ(off));
                    bh[nt][1] = *(const uint32_t*)(tBh + SWZ(off + 16));
                    bl[nt][0] = *(const uint32_t*)(tBl + SWZ(off));
                    bl[nt][1] = *(const uint32_t*)(tBl + SWZ(off + 16));
                }
#pragma unroll
                for (int mt = 0; mt < 2; mt++) {
                    uint32_t o0 = (uint32_t)((wm + mt * 16 + lg) * 128) + kbase;
                    uint32_t o8 = o0 + 8 * 128;
                    uint32_t ah[4] = {
                        *(const uint32_t*)(tAh + SWZ(o0)),      *(const uint32_t*)(tAh + SWZ(o8)),
                        *(const uint32_t*)(tAh + SWZ(o0 + 16)), *(const uint32_t*)(tAh + SWZ(o8 + 16)) };
                    uint32_t al[4] = {
                        *(const uint32_t*)(tAl + SWZ(o0)),      *(const uint32_t*)(tAl + SWZ(o8)),
                        *(const uint32_t*)(tAl + SWZ(o0 + 16)), *(const uint32_t*)(tAl + SWZ(o8 + 16)) };
#pragma unroll
                    for (int nt = 0; nt < 8; nt++) mma16816(acc[mt][nt], ah, bh[nt]);
#pragma unroll
                    for (int nt = 0; nt < 8; nt++) mma16816(acc[mt][nt], ah, bl[nt]);
#pragma unroll
                    for (int nt = 0; nt < 8; nt++) mma16816(acc[mt][nt], al, bh[nt]);
                }
            }
            __syncthreads();
        }

#pragma unroll
        for (int mt = 0; mt < 2; mt++) {
#pragma unroll
            for (int nt = 0; nt < 8; nt++) {
                int row = bm + wm + mt * 16 + lg;
                int col = bn + nh * 128 + wn + nt * 8 + lt * 2;
                float b0 = bias ? bias[col]     : 0.f;
                float b1 = bias ? bias[col + 1] : 0.f;
                float2 v0 = { acc[mt][nt][0] * alpha + b0, acc[mt][nt][1] * alpha + b1 };
                float2 v1 = { acc[mt][nt][2] * alpha + b0, acc[mt][nt][3] * alpha + b1 };
                *(float2*)(C + (size_t)row * N + col)       = v0;
                *(float2*)(C + (size_t)(row + 8) * N + col) = v1;
            }
        }
        __syncthreads();
    }
#endif
}

// ---------------------------------------------------------------------------
// fp32 -> (hi, lo) bf16 split, vectorized by 4
// ---------------------------------------------------------------------------
__device__ __forceinline__ void split4(const float4 v,
                                       __nv_bfloat16* hi, __nv_bfloat16* lo, int i)
{
    __nv_bfloat16 h0 = __float2bfloat16(v.x), h1 = __float2bfloat16(v.y);
    __nv_bfloat16 h2 = __float2bfloat16(v.z), h3 = __float2bfloat16(v.w);
    __nv_bfloat16 l0 = __float2bfloat16(v.x - __bfloat162float(h0));
    __nv_bfloat16 l1 = __float2bfloat16(v.y - __bfloat162float(h1));
    __nv_bfloat16 l2 = __float2bfloat16(v.z - __bfloat162float(h2));
    __nv_bfloat16 l3 = __float2bfloat16(v.w - __bfloat162float(h3));
    ushort4 ph = { __bfloat16_as_ushort(h0), __bfloat16_as_ushort(h1),
                   __bfloat16_as_ushort(h2), __bfloat16_as_ushort(h3) };
    ushort4 pl = { __bfloat16_as_ushort(l0), __bfloat16_as_ushort(l1),
                   __bfloat16_as_ushort(l2), __bfloat16_as_ushort(l3) };
    ((ushort4*)hi)[i] = ph;
    ((ushort4*)lo)[i] = pl;
}

__global__ __launch_bounds__(256)
void split32(const float* __restrict__ s, __nv_bfloat16* __restrict__ hi,
             __nv_bfloat16* __restrict__ lo)
{
    int i = blockIdx.x * blockDim.x + threadIdx.x;
    split4(((const float4*)s)[i], hi, lo, i);
}

// One launch splitting all five weight matrices.
__global__ __launch_bounds__(256)
void split_w(const float* __restrict__ Wq, const float* __restrict__ Wk,
             const float* __restrict__ Wv, const float* __restrict__ Wg,
             const float* __restrict__ Wo,
             __nv_bfloat16* __restrict__ wqh, __nv_bfloat16* __restrict__ wql,
             __nv_bfloat16* __restrict__ wkh, __nv_bfloat16* __restrict__ wkl,
             __nv_bfloat16* __restrict__ wvh, __nv_bfloat16* __restrict__ wvl,
             __nv_bfloat16* __restrict__ wgh, __nv_bfloat16* __restrict__ wgl,
             __nv_bfloat16* __restrict__ woh, __nv_bfloat16* __restrict__ wol)
{
    int b = blockIdx.x;
    const float* src; __nv_bfloat16 *hi, *lo;
    if      (b < 2048)  { src = Wq; hi = wqh; lo = wql; }
    else if (b < 4096)  { src = Wk; hi = wkh; lo = wkl; b -= 2048; }
    else if (b < 8192)  { src = Wv; hi = wvh; lo = wvl; b -= 4096; }
    else if (b < 12288) { src = Wg; hi = wgh; lo = wgl; b -= 8192; }
    else                { src = Wo; hi = woh; lo = wol; b -= 12288; }
    int i = b * 256 + threadIdx.x;
    split4(((const float4*)src)[i], hi, lo, i);
}

// ---------------------------------------------------------------------------
// Low-rank gate (fp32 SIMT — tiny)
// ---------------------------------------------------------------------------
__global__ void kg_gemm1(const float* __restrict__ x, const float* __restrict__ W,
                         float* __restrict__ t16)
{
    int idx = blockIdx.x * blockDim.x + threadIdx.x;   // 4096*16
    int m = idx >> 4, n = idx & 15;
    const float* xr = x + (size_t)m * DMODEL;
    const float* wr = W + (size_t)n * DMODEL;
    float acc = 0.f;
#pragma unroll 4
    for (int kk = 0; kk < DMODEL; kk += 4) {
        float4 a = *(const float4*)(xr + kk);
        float4 b = *(const float4*)(wr + kk);
        acc += a.x * b.x + a.y * b.y + a.z * b.z + a.w * b.w;
    }
    t16[idx] = acc;
}

__global__ void kg_gemm2(const float* __restrict__ t16, const float* __restrict__ W2,
                         const float* __restrict__ b2, float* __restrict__ kg)
{
    int idx = blockIdx.x * blockDim.x + threadIdx.x;   // 4096*1024
    int m = idx >> 10, n = idx & 1023;
    const float* tr = t16 + (size_t)m * 16;
    const float* wr = W2 + (size_t)n * 16;
    float acc = b2[n];
#pragma unroll
    for (int c = 0; c < 16; c++) acc = fmaf(tr[c], wr[c], acc);
    kg[idx] = acc;
}

// ---------------------------------------------------------------------------
// GLA recurrence. One block per (b, head, dv-chunk of 32). float4 staged loads.
// ---------------------------------------------------------------------------
#define TT 16
__global__ __launch_bounds__(256)
void gla_rec(const float* __restrict__ q, const float* __restrict__ k,
             const float* __restrict__ kg, const float* __restrict__ v,
             float* __restrict__ o)
{
    const int blk   = blockIdx.x;       // 128 = B * H * 4
    const int chunk = blk & 3;
    const int head  = (blk >> 2) & 15;
    const int b     = blk >> 6;
    const int j0    = chunk * 32;

    const int tid = threadIdx.x;
    const int j   = tid >> 3;           // 0..31
    const int ig  = tid & 7;            // 0..7

    __shared__ __align__(16) float qs[TT][DK];
    __shared__ __align__(16) float ks[TT][DK];
    __shared__ __align__(16) float es[TT][DK];
    __shared__ __align__(16) float vs[TT][32];

    const float* qb = q  + (size_t)b * SEQ * DQK    + head * DK;
    const float* kb = k  + (size_t)b * SEQ * DQK    + head * DK;
    const float* gb = kg + (size_t)b * SEQ * DQK    + head * DK;
    const float* vb = v  + (size_t)b * SEQ * DMODEL + head * DV + j0;
    float*       ob = o  + (size_t)b * SEQ * DMODEL + head * DV + j0;

    const int ltt = tid >> 4;           // row 0..15
    const int lu  = tid & 15;           // float4 col 0..15
    const int vtt = tid >> 3;
    const int vu  = tid & 7;

    float S[8] = {0.f, 0.f, 0.f, 0.f, 0.f, 0.f, 0.f, 0.f};

    for (int t0 = 0; t0 < SEQ; t0 += TT) {
        {
            size_t r4 = (size_t)(t0 + ltt) * (DQK / 4) + lu;
            float4 qv = ((const float4*)qb)[r4];
            float4 kv = ((const float4*)kb)[r4];
            float4 gv = ((const float4*)gb)[r4];
            *(float4*)&qs[ltt][lu * 4] = qv;
            *(float4*)&ks[ltt][lu * 4] = kv;
            float4 ev;
            {
                float a0 = fminf(gv.x, 0.f) - log1pf(__expf(-fabsf(gv.x)));
                float a1 = fminf(gv.y, 0.f) - log1pf(__expf(-fabsf(gv.y)));
                float a2 = fminf(gv.z, 0.f) - log1pf(__expf(-fabsf(gv.z)));
                float a3 = fminf(gv.w, 0.f) - log1pf(__expf(-fabsf(gv.w)));
                ev.x = __expf(a0 * INV_NORM); ev.y = __expf(a1 * INV_NORM);
                ev.z = __expf(a2 * INV_NORM); ev.w = __expf(a3 * INV_NORM);
            }
            *(float4*)&es[ltt][lu * 4] = ev;
            if (tid < 128) {
                float4 vv = ((const float4*)vb)[(size_t)(t0 + vtt) * (DMODEL / 4) + vu];
                *(float4*)&vs[vtt][vu * 4] = vv;
            }
        }
        __syncthreads();

        for (int tt = 0; tt < TT; tt++) {
            float vj  = vs[tt][j];
            float acc = 0.f;
#pragma unroll
            for (int r = 0; r < 8; r++) {
                int i = ig * 8 + r;
                float s = fmaf(S[r], es[tt][i], ks[tt][i] * vj);
                S[r] = s;
                acc = fmaf(qs[tt][i], s, acc);
            }
            acc += __shfl_xor_sync(0xffffffffu, acc, 4);
            acc += __shfl_xor_sync(0xffffffffu, acc, 2);
            acc += __shfl_xor_sync(0xffffffffu, acc, 1);
            if (ig == 0) ob[(size_t)(t0 + tt) * DMODEL + j] = acc;
        }
        __syncthreads();
    }
}

// ---------------------------------------------------------------------------
// LayerNorm(dv=128, no affine) + SiLU gate, fused hi/lo bf16 split of z
// ---------------------------------------------------------------------------
__global__ __launch_bounds__(256)
void ln_gate(const float* __restrict__ o, const float* __restrict__ gp,
             __nv_bfloat16* __restrict__ zh, __nv_bfloat16* __restrict__ zl)
{
    int gw   = (blockIdx.x * blockDim.x + threadIdx.x) >> 5;   // row id, 65536 total
    int lane = threadIdx.x & 31;

    float4 ov = ((const float4*)(o + (size_t)gw * 128))[lane];
    float s = ov.x + ov.y + ov.z + ov.w;
#pragma unroll
    for (int d = 16; d > 0; d >>= 1) s += __shfl_xor_sync(0xffffffffu, s, d);
    float mu = s * (1.f / 128.f);

    float dx0 = ov.x - mu, dx1 = ov.y - mu, dx2 = ov.z - mu, dx3 = ov.w - mu;
    float vsum = dx0 * dx0 + dx1 * dx1 + dx2 * dx2 + dx3 * dx3;
#pragma unroll
    for (int d = 16; d > 0; d >>= 1) vsum += __shfl_xor_sync(0xffffffffu, vsum, d);
    float inv = rsqrtf(vsum * (1.f / 128.f) + 1e-5f);

    float4 gv = ((const float4*)(gp + (size_t)gw * 128))[lane];
    float4 z;
    z.x = (gv.x / (1.f + __expf(-gv.x))) * (dx0 * inv);
    z.y = (gv.y / (1.f + __expf(-gv.y))) * (dx1 * inv);
    z.z = (gv.z / (1.f + __expf(-gv.z))) * (dx2 * inv);
    z.w = (gv.w / (1.f + __expf(-gv.w))) * (dx3 * inv);
    split4(z, zh, zl, gw * 32 + lane);
}

// ---------------------------------------------------------------------------
extern "C" void kernel_launch(void* const* d_in, const int* in_sizes, int n_in,
                              void* d_out, int out_size)
{
    const float* x    = (const float*)d_in[0];
    const float* Wq   = (const float*)d_in[1];
    const float* Wk   = (const float*)d_in[2];
    const float* Wkg1 = (const float*)d_in[3];
    const float* Wkg2 = (const float*)d_in[4];
    const float* bkg2 = (const float*)d_in[5];
    const float* Wv   = (const float*)d_in[6];
    const float* Wg   = (const float*)d_in[7];
    const float* bg   = (const float*)d_in[8];
    const float* Wo   = (const float*)d_in[9];
    float* out = (float*)d_out;

    float *q, *k, *kg, *v, *gp, *o, *t16;
    cudaGetSymbolAddress((void**)&q,   g_q);
    cudaGetSymbolAddress((void**)&k,   g_k);
    cudaGetSymbolAddress((void**)&kg,  g_kg);
    cudaGetSymbolAddress((void**)&v,   g_v);
    cudaGetSymbolAddress((void**)&gp,  g_gp);
    cudaGetSymbolAddress((void**)&o,   g_o);
    cudaGetSymbolAddress((void**)&t16, g_t16);

    __nv_bfloat16 *xh, *xl, *zh, *zl;
    __nv_bfloat16 *wqh, *wql, *wkh, *wkl, *wvh, *wvl, *wgh, *wgl, *woh, *wol;
    cudaGetSymbolAddress((void**)&xh,  g_xh);  cudaGetSymbolAddress((void**)&xl,  g_xl);
    cudaGetSymbolAddress((void**)&zh,  g_zh);  cudaGetSymbolAddress((void**)&zl,  g_zl);
    cudaGetSymbolAddress((void**)&wqh, g_wqh); cudaGetSymbolAddress((void**)&wql, g_wql);
    cudaGetSymbolAddress((void**)&wkh, g_wkh); cudaGetSymbolAddress((void**)&wkl, g_wkl);
    cudaGetSymbolAddress((void**)&wvh, g_wvh); cudaGetSymbolAddress((void**)&wvl, g_wvl);
    cudaGetSymbolAddress((void**)&wgh, g_wgh); cudaGetSymbolAddress((void**)&wgl, g_wgl);
    cudaGetSymbolAddress((void**)&woh, g_woh); cudaGetSymbolAddress((void**)&wol, g_wol);

    cudaFuncSetAttribute(gemm3, cudaFuncAttributeMaxDynamicSharedMemorySize, GEMM_DSM);

    // hi/lo splits: 2 launches
    split32<<<(MTOK * DMODEL) / 1024, 256>>>(x, xh, xl);
    split_w<<<16384, 256>>>(Wq, Wk, Wv, Wg, Wo,
                            wqh, wql, wkh, wkl, wvh, wvl, wgh, wgl, woh, wol);

    dim3 blk(256);
    dim3 gQK(DQK / 256, MTOK / 128);      // 4 x 32
    dim3 gD (DMODEL / 256, MTOK / 128);   // 8 x 32

    gemm3<<<gQK, blk, GEMM_DSM>>>(xh, xl, wqh, wql, nullptr, q,  DQK,    DMODEL, 1.f);
    gemm3<<<gQK, blk, GEMM_DSM>>>(xh, xl, wkh, wkl, nullptr, k,  DQK,    DMODEL, SCALE_K);
    gemm3<<<gD,  blk, GEMM_DSM>>>(xh, xl, wvh, wvl, nullptr, v,  DMODEL, DMODEL, 1.f);
    gemm3<<<gD,  blk, GEMM_DSM>>>(xh, xl, wgh, wgl, bg,      gp, DMODEL, DMODEL, 1.f);  // <- ncu -s 5

    kg_gemm1<<<(MTOK * 16) / 256, 256>>>(x, Wkg1, t16);
    kg_gemm2<<<(MTOK * DQK) / 256, 256>>>(t16, Wkg2, bkg2, kg);

    gla_rec<<<128, 256>>>(q, k, kg, v, o);

    ln_gate<<<(MTOK * NHEAD * 32) / 256, 256>>>(o, gp, zh, zl);

    gemm3<<<gD, blk, GEMM_DSM>>>(zh, zl, woh, wol, nullptr, out, DMODEL, DMODEL, 1.f);
}

// round 7
// speedup vs baseline: 1.0494x; 1.0494x over previous
#include <cuda_runtime.h>
#include <cuda_bf16.h>
#include <math.h>
#include <cstdint>

// ---------------------------------------------------------------------------
// Problem constants: B=2, L=2048, D=2048, H=16, dk=64, dv=128.  M = B*L = 4096.
// ---------------------------------------------------------------------------
#define MTOK 4096
#define DMODEL 2048
#define DQK 1024
#define NHEAD 16
#define DK 64
#define DV 128
#define SEQ 2048
#define SCALE_K 0.08838834764831845f   // 128^-0.5
#define INV_NORM 0.0625f               // 1/16

// tcgen05 only exists in the arch-specific (sm_103a) compilation pass.
#if defined(__CUDA_ARCH__) && (__CUDA_ARCH__ == 1030) && defined(__CUDA_ARCH_FEAT_SM103_ALL)
#define USE_TCGEN05 1
#else
#define USE_TCGEN05 0
#endif

// ---------------------------------------------------------------------------
// Scratch (device globals: no allocation allowed)
// ---------------------------------------------------------------------------
__device__ float g_q [MTOK * DQK];
__device__ float g_k [MTOK * DQK];
__device__ float g_kg[MTOK * DQK];
__device__ float g_v [MTOK * DMODEL];
__device__ float g_gp[MTOK * DMODEL];
__device__ float g_o [MTOK * DMODEL];
__device__ float g_t16[MTOK * 16];

__device__ __nv_bfloat16 g_xh[MTOK * DMODEL],   g_xl[MTOK * DMODEL];
__device__ __nv_bfloat16 g_zh[MTOK * DMODEL],   g_zl[MTOK * DMODEL];
__device__ __nv_bfloat16 g_wqh[DQK * DMODEL],   g_wql[DQK * DMODEL];
__device__ __nv_bfloat16 g_wkh[DQK * DMODEL],   g_wkl[DQK * DMODEL];
__device__ __nv_bfloat16 g_wvh[DMODEL * DMODEL], g_wvl[DMODEL * DMODEL];
__device__ __nv_bfloat16 g_wgh[DMODEL * DMODEL], g_wgl[DMODEL * DMODEL];
__device__ __nv_bfloat16 g_woh[DMODEL * DMODEL], g_wol[DMODEL * DMODEL];

// ---------------------------------------------------------------------------
// PTX helpers
// ---------------------------------------------------------------------------
__device__ __forceinline__ uint32_t smem_u32(const void* p) {
    uint32_t a;
    asm("{ .reg .u64 t; cvta.to.shared.u64 t, %1; cvt.u32.u64 %0, t; }" : "=r"(a) : "l"(p));
    return a;
}

#define SWZ(o) ((o) ^ (((o) >> 3) & 0x70))

#define CP_ASYNC16(dst, src) \
    asm volatile("cp.async.cg.shared.global [%0], [%1], 16;" :: "r"(dst), "l"(src))
// Arrive-on-complete of ALL prior cp.async by this thread; .noinc counts
// against the barrier's initialized expected-arrival count (pipeline idiom).
#define CP_ASYNC_MBAR_ARRIVE(mb) \
    asm volatile("cp.async.mbarrier.arrive.noinc.shared.b64 [%0];" :: "r"((uint32_t)(mb)) : "memory")
#define CP_ASYNC_COMMIT() \
    asm volatile("cp.async.commit_group;" ::: "memory")
#define CP_ASYNC_WAIT(n) \
    asm volatile("cp.async.wait_group %0;" :: "n"(n) : "memory")

#define MBARRIER_INIT(mb, cnt) \
    asm volatile("mbarrier.init.shared.b64 [%0], %1;" :: "r"((uint32_t)(mb)), "r"((uint32_t)(cnt)) : "memory")

#define MBARRIER_WAIT_PARITY(mb, par) do { \
    uint32_t _mb = (uint32_t)(mb); uint32_t _p = (uint32_t)(par); uint32_t _done; \
    asm volatile("{\n\t.reg .pred p;\n\t" \
        "mbarrier.try_wait.parity.acquire.cta.shared::cta.b64 p, [%1], %2;\n\t" \
        "selp.b32 %0, 1, 0, p;\n\t}" : "=r"(_done) : "r"(_mb), "r"(_p) : "memory"); \
    if (!_done) { \
        asm volatile("{\n\t.reg .pred P1;\n\t" \
            "WL_%=:\n\t" \
            "mbarrier.try_wait.parity.acquire.cta.shared::cta.b64 P1, [%0], %1, 0x989680;\n\t" \
            "@P1 bra.uni WD_%=;\n\t" \
            "bra.uni WL_%=;\n\t" \
            "WD_%=:\n\t}" :: "r"(_mb), "r"(_p) : "memory"); \
    } \
} while (0)

#if USE_TCGEN05
__device__ __forceinline__ uint32_t elect_one_pred() {
    uint32_t pred;
    asm volatile("{\n\t.reg .pred p;\n\telect.sync _|p, 0xFFFFFFFF;\n\t"
                 "selp.b32 %0, 1, 0, p;\n\t}" : "=r"(pred));
    return pred;
}

#define TCGEN05_ALLOC(smem_res, ncols) \
    asm volatile("tcgen05.alloc.cta_group::1.sync.aligned.shared::cta.b32 [%0], %1;" \
                 :: "r"((uint32_t)(smem_res)), "r"((uint32_t)(ncols)) : "memory")
#define TCGEN05_DEALLOC(tm, ncols) \
    asm volatile("tcgen05.dealloc.cta_group::1.sync.aligned.b32 %0, %1;" :: "r"(tm), "r"((uint32_t)(ncols)))
#define TCGEN05_RELINQ() \
    asm volatile("tcgen05.relinquish_alloc_permit.cta_group::1.sync.aligned;")
#define TCGEN05_COMMIT(mb) \
    asm volatile("tcgen05.commit.cta_group::1.mbarrier::arrive::one.shared::cluster.b64 [%0];" \
                 :: "r"((uint32_t)(mb)) : "memory")
#define TCGEN05_FENCE_AFTER() \
    asm volatile("tcgen05.fence::after_thread_sync;" ::: "memory")
#define TCGEN05_WAIT_LD() \
    asm volatile("tcgen05.wait::ld.sync.aligned;" ::: "memory")
#define FENCE_PROXY_ASYNC() \
    asm volatile("fence.proxy.async.shared::cta;" ::: "memory")

#define TCGEN05_LD_X32(r, tm) \
    asm volatile("tcgen05.ld.sync.aligned.32x32b.x32.b32 " \
        "{%0, %1, %2, %3, %4, %5, %6, %7, %8, %9, %10, %11, %12, %13, %14, %15, " \
        " %16, %17, %18, %19, %20, %21, %22, %23, %24, %25, %26, %27, %28, %29, %30, %31}, [%32];" \
        : "=r"((r)[0]),  "=r"((r)[1]),  "=r"((r)[2]),  "=r"((r)[3]), \
          "=r"((r)[4]),  "=r"((r)[5]),  "=r"((r)[6]),  "=r"((r)[7]), \
          "=r"((r)[8]),  "=r"((r)[9]),  "=r"((r)[10]), "=r"((r)[11]), \
          "=r"((r)[12]), "=r"((r)[13]), "=r"((r)[14]), "=r"((r)[15]), \
          "=r"((r)[16]), "=r"((r)[17]), "=r"((r)[18]), "=r"((r)[19]), \
          "=r"((r)[20]), "=r"((r)[21]), "=r"((r)[22]), "=r"((r)[23]), \
          "=r"((r)[24]), "=r"((r)[25]), "=r"((r)[26]), "=r"((r)[27]), \
          "=r"((r)[28]), "=r"((r)[29]), "=r"((r)[30]), "=r"((r)[31]) \
        : "r"(tm))

// K-major SW128 descriptor: layout=2 (SW128), version=1, SBO=64, LBO=1
static constexpr uint64_t DESC_BASE_SW128 =
    (uint64_t(2) << 61) | (uint64_t(1) << 46) | (uint64_t(64) << 32) | (uint64_t(1) << 16);
#define MAKE_DESC(addr) (DESC_BASE_SW128 | ((uint64_t)((addr) >> 4) & 0x3FFF))

__device__ __forceinline__ void mma_f16_ss(uint32_t d, uint64_t ad, uint64_t bd,
                                           uint32_t idesc, uint32_t en) {
    asm volatile("{\n\t.reg .pred p;\n\tsetp.ne.u32 p, %5, 0;\n\t"
        "tcgen05.mma.cta_group::1.kind::f16 [%0], %1, %2, %3, {%4, %4, %4, %4}, p;\n\t}"
        :: "r"(d), "l"(ad), "l"(bd), "r"(idesc), "r"(0u), "r"(en) : "memory");
}
#else
// HMMA fallback primitive: m16n8k16 row.col bf16 -> f32
__device__ __forceinline__ void mma16816(float* d, const uint32_t* a, const uint32_t* b) {
    asm volatile("mma.sync.aligned.m16n8k16.row.col.f32.bf16.bf16.f32 "
        "{%0,%1,%2,%3}, {%4,%5,%6,%7}, {%8,%9}, {%0,%1,%2,%3};"
        : "+f"(d[0]), "+f"(d[1]), "+f"(d[2]), "+f"(d[3])
        : "r"(a[0]), "r"(a[1]), "r"(a[2]), "r"(a[3]), "r"(b[0]), "r"(b[1]));
}
#endif

// ---------------------------------------------------------------------------
// bf16x3 GEMM:  C[M,N] = alpha * (A @ B^T) (+ bias), split hi/lo operands.
// Tile 128x256 (two N=128 MMA halves), K-chunk 64, WARP-SPECIALIZED:
//   threads 0..255  = loaders (cp.async + noinc mbarrier arrive)
//   warp 8 (256..287) = MMA warp (full-wait -> 24 MMA -> commit -> empty)
// No __syncthreads in the mainloop; tensor pipe stays fed.
// Buffer layout per stage: Ah 16K | Al 16K | Bh 32K | Bl 32K = 96KB.
// ---------------------------------------------------------------------------
#define BUFB 98304
#define GEMM_DSM (2 * BUFB + 1024)
#define GEMM_THREADS 288

__global__ __launch_bounds__(GEMM_THREADS) __cluster_dims__(1, 1, 1)
void gemm3(const __nv_bfloat16* __restrict__ Ah, const __nv_bfloat16* __restrict__ Al,
           const __nv_bfloat16* __restrict__ Bh, const __nv_bfloat16* __restrict__ Bl,
           const float* __restrict__ bias, float* __restrict__ C,
           int N, int K, float alpha)
{
    extern __shared__ char dsm[];

    const int tid = threadIdx.x;
    const int bm = blockIdx.y * 128;
    const int bn = blockIdx.x * 256;

    const uint32_t raw = smem_u32(dsm);
    const uint32_t sbase = (raw + 1023u) & ~1023u;
    char* sgen = dsm + (sbase - raw);

    const int NC = K / 64;

#if USE_TCGEN05
    __shared__ uint32_t s_tmem;
    __shared__ __align__(16) uint64_t s_full[2];
    __shared__ __align__(16) uint64_t s_empty[2];
    const uint32_t full0  = smem_u32(&s_full[0]),  full1  = smem_u32(&s_full[1]);
    const uint32_t empty0 = smem_u32(&s_empty[0]), empty1 = smem_u32(&s_empty[1]);

    if (tid < 32) { TCGEN05_ALLOC(smem_u32(&s_tmem), 256); TCGEN05_RELINQ(); }
    if (tid == 0) {
        MBARRIER_INIT(full0, 256);  MBARRIER_INIT(full1, 256);
        MBARRIER_INIT(empty0, 1);   MBARRIER_INIT(empty1, 1);
    }
    __syncthreads();
    const uint32_t tmem = s_tmem;

    if (tid < 256) {
        // ---------------- loader role ----------------
        const int lr  = tid >> 3;          // 0..31 base row
        const int seg = tid & 7;           // 16B segment within 128B row
        for (int c = 0; c < NC; c++) {
            if (c >= 2)
                MBARRIER_WAIT_PARITY((c & 1) ? empty1 : empty0, ((c - 2) >> 1) & 1);
            const uint32_t bb = sbase + (c & 1) * BUFB;
            const int k0 = c * 64;
#pragma unroll
            for (int t2 = 0; t2 < 2; t2++) {               // Ah, Al (128 rows)
                const __nv_bfloat16* basep = t2 ? Al : Ah;
                uint32_t tb = bb + t2 * 16384;
#pragma unroll
                for (int ii = 0; ii < 4; ii++) {
                    int r = lr + ii * 32;
                    const void* src = basep + (size_t)(bm + r) * K + k0 + seg * 8;
                    CP_ASYNC16(tb + SWZ((uint32_t)(r * 128 + seg * 16)), src);
                }
            }
#pragma unroll
            for (int t2 = 0; t2 < 2; t2++) {               // Bh, Bl (256 rows)
                const __nv_bfloat16* basep = t2 ? Bl : Bh;
                uint32_t tb = bb + 32768 + t2 * 32768;
#pragma unroll
                for (int ii = 0; ii < 8; ii++) {
                    int r = lr + ii * 32;
                    const void* src = basep + (size_t)(bn + r) * K + k0 + seg * 8;
                    CP_ASYNC16(tb + SWZ((uint32_t)(r * 128 + seg * 16)), src);
                }
            }
            CP_ASYNC_MBAR_ARRIVE((c & 1) ? full1 : full0);
        }
    } else if (elect_one_pred()) {
        // ---------------- MMA role (single elected thread of warp 8) --------
        const uint32_t IDESC = (1u << 4) | (1u << 7) | (1u << 10) | (16u << 17) | (8u << 24);
        for (int c = 0; c < NC; c++) {
            MBARRIER_WAIT_PARITY((c & 1) ? full1 : full0, (c >> 1) & 1);
            FENCE_PROXY_ASYNC();           // generic (cp.async) -> async proxy
            const uint32_t ab = sbase + (c & 1) * BUFB;
            const uint64_t dAh  = MAKE_DESC(ab);
            const uint64_t dAl  = MAKE_DESC(ab + 16384);
            const uint64_t dBh0 = MAKE_DESC(ab + 32768);
            const uint64_t dBh1 = MAKE_DESC(ab + 32768 + 16384);
            const uint64_t dBl0 = MAKE_DESC(ab + 65536);
            const uint64_t dBl1 = MAKE_DESC(ab + 65536 + 16384);
            const uint32_t en0 = (c > 0);
#pragma unroll
            for (int ks = 0; ks < 4; ks++)
                mma_f16_ss(tmem,       dAh + ks * 2, dBh0 + ks * 2, IDESC, en0 || (ks > 0));
#pragma unroll
            for (int ks = 0; ks < 4; ks++)
                mma_f16_ss(tmem + 128, dAh + ks * 2, dBh1 + ks * 2, IDESC, en0 || (ks > 0));
#pragma unroll
            for (int ks = 0; ks < 4; ks++) {
                mma_f16_ss(tmem,       dAh + ks * 2, dBl0 + ks * 2, IDESC, 1u);
                mma_f16_ss(tmem + 128, dAh + ks * 2, dBl1 + ks * 2, IDESC, 1u);
                mma_f16_ss(tmem,       dAl + ks * 2, dBh0 + ks * 2, IDESC, 1u);
                mma_f16_ss(tmem + 128, dAl + ks * 2, dBh1 + ks * 2, IDESC, 1u);
            }
            TCGEN05_COMMIT((c & 1) ? empty1 : empty0);
        }
    }

    __syncthreads();
    // final MMA chunk NC-1: completion #((NC-1)>>1) on empty[(NC-1)&1]
    MBARRIER_WAIT_PARITY(((NC - 1) & 1) ? empty1 : empty0, ((NC - 1) >> 1) & 1);
    TCGEN05_FENCE_AFTER();
    __syncthreads();

    // epilogue: TMEM -> regs -> padded SMEM stage -> coalesced STG (8 slabs)
    float* stage = (float*)sgen;
    for (int slab = 0; slab < 8; slab++) {
        if (tid < 128) {
            uint32_t regs[32];
            TCGEN05_LD_X32(regs, tmem + slab * 32);
            TCGEN05_WAIT_LD();
#pragma unroll
            for (int cc = 0; cc < 32; cc++) stage[tid * 33 + cc] = __uint_as_float(regs[cc]);
        }
        __syncthreads();
        for (int e = tid; e < 4096; e += GEMM_THREADS) {
            int row = e >> 5, col = e & 31;
            float vv = stage[row * 33 + col] * alpha;
            if (bias) vv += bias[bn + slab * 32 + col];
            C[(size_t)(bm + row) * N + bn + slab * 32 + col] = vv;
        }
        __syncthreads();
    }
    if (tid < 32) TCGEN05_DEALLOC(tmem, 256);

#else  // ------------------- HMMA mma.sync fallback ------------------------
    const int warp = tid >> 5;
    const int lane = tid & 31;
    if (warp < 8) {
        const int wm = (warp & 3) * 32;
        const int wn = (warp >> 2) * 64;
        const int lg = lane >> 2;
        const int lt = lane & 3;
        const int lr  = tid >> 3;
        const int seg = tid & 7;

        auto load_chunk = [&](int c) {
            uint32_t bb = sbase + (c & 1) * BUFB;
            const int k0 = c * 64;
#pragma unroll
            for (int t2 = 0; t2 < 2; t2++) {
                const __nv_bfloat16* basep = t2 ? Al : Ah;
                uint32_t tb = bb + t2 * 16384;
#pragma unroll
                for (int ii = 0; ii < 4; ii++) {
                    int r = lr + ii * 32;
                    const void* src = basep + (size_t)(bm + r) * K + k0 + seg * 8;
                    CP_ASYNC16(tb + SWZ((uint32_t)(r * 128 + seg * 16)), src);
                }
            }
#pragma unroll
            for (int t2 = 0; t2 < 2; t2++) {
                const __nv_bfloat16* basep = t2 ? Bl : Bh;
                uint32_t tb = bb + 32768 + t2 * 32768;
#pragma unroll
                for (int ii = 0; ii < 8; ii++) {
                    int r = lr + ii * 32;
                    const void* src = basep + (size_t)(bn + r) * K + k0 + seg * 8;
                    CP_ASYNC16(tb + SWZ((uint32_t)(r * 128 + seg * 16)), src);
                }
            }
            CP_ASYNC_COMMIT();
        };

        for (int nh = 0; nh < 2; nh++) {
            float acc[2][8][4];
#pragma unroll
            for (int mt = 0; mt < 2; mt++)
#pragma unroll
                for (int nt = 0; nt < 8; nt++)
#pragma unroll
                    for (int r = 0; r < 4; r++) acc[mt][nt][r] = 0.f;

            load_chunk(0);
            for (int c = 0; c < NC; c++) {
                if (c + 1 < NC) { load_chunk(c + 1); CP_ASYNC_WAIT(1); }
                else            { CP_ASYNC_WAIT(0); }
                asm volatile("bar.sync 1, 256;" ::: "memory");

                char* bb = sgen + (c & 1) * BUFB;
                char* tAh = bb, *tAl = bb + 16384;
                char* tBh = bb + 32768 + nh * 16384, *tBl = bb + 65536 + nh * 16384;
#pragma unroll
                for (int kk = 0; kk < 64; kk += 16) {
                    const uint32_t kbase = (kk + lt * 2) * 2;
                    uint32_t bh[8][2], bl[8][2];
#pragma unroll
                    for (int nt = 0; nt < 8; nt++) {
                        uint32_t off = (uint32_t)((wn + nt * 8 + lg) * 128) + kbase;
                        bh[nt][0] = *(const uint32_t*)(tBh + SWZ(off));
                        bh[nt][1] = *(const uint32_t*)(tBh + SWZ(off + 16));
                        bl[nt][0] = *(const uint32_t*)(tBl + SWZ(off));
                        bl[nt][1] = *(const uint32_t*)(tBl + SWZ(off + 16));
                    }
#pragma unroll
                    for (int mt = 0; mt < 2; mt++) {
                        uint32_t o0 = (uint32_t)((wm + mt * 16 + lg) * 128) + kbase;
                        uint32_t o8 = o0 + 8 * 128;
                        uint32_t ah[4] = {
                            *(const uint32_t*)(tAh + SWZ(o0)),      *(const uint32_t*)(tAh + SWZ(o8)),
                            *(const uint32_t*)(tAh + SWZ(o0 + 16)), *(const uint32_t*)(tAh + SWZ(o8 + 16)) };
                        uint32_t al[4] = {
                            *(const uint32_t*)(tAl + SWZ(o0)),      *(const uint32_t*)(tAl + SWZ(o8)),
                            *(const uint32_t*)(tAl + SWZ(o0 + 16)), *(const uint32_t*)(tAl + SWZ(o8 + 16)) };
#pragma unroll
                        for (int nt = 0; nt < 8; nt++) mma16816(acc[mt][nt], ah, bh[nt]);
#pragma unroll
                        for (int nt = 0; nt < 8; nt++) mma16816(acc[mt][nt], ah, bl[nt]);
#pragma unroll
                        for (int nt = 0; nt < 8; nt++) mma16816(acc[mt][nt], al, bh[nt]);
                    }
                }
                asm volatile("bar.sync 1, 256;" ::: "memory");
            }
#pragma unroll
            for (int mt = 0; mt < 2; mt++) {
#pragma unroll
                for (int nt = 0; nt < 8; nt++) {
                    int row = bm + wm + mt * 16 + lg;
                    int col = bn + nh * 128 + wn + nt * 8 + lt * 2;
                    float b0 = bias ? bias[col]     : 0.f;
                    float b1 = bias ? bias[col + 1] : 0.f;
                    float2 v0 = { acc[mt][nt][0] * alpha + b0, acc[mt][nt][1] * alpha + b1 };
                    float2 v1 = { acc[mt][nt][2] * alpha + b0, acc[mt][nt][3] * alpha + b1 };
                    *(float2*)(C + (size_t)row * N + col)       = v0;
                    *(float2*)(C + (size_t)(row + 8) * N + col) = v1;
                }
            }
            asm volatile("bar.sync 1, 256;" ::: "memory");
        }
    }
#endif
}

// ---------------------------------------------------------------------------
// fp32 -> (hi, lo) bf16 split, vectorized by 4
// ---------------------------------------------------------------------------
__device__ __forceinline__ void split4(const float4 v,
                                       __nv_bfloat16* hi, __nv_bfloat16* lo, int i)
{
    __nv_bfloat16 h0 = __float2bfloat16(v.x), h1 = __float2bfloat16(v.y);
    __nv_bfloat16 h2 = __float2bfloat16(v.z), h3 = __float2bfloat16(v.w);
    __nv_bfloat16 l0 = __float2bfloat16(v.x - __bfloat162float(h0));
    __nv_bfloat16 l1 = __float2bfloat16(v.y - __bfloat162float(h1));
    __nv_bfloat16 l2 = __float2bfloat16(v.z - __bfloat162float(h2));
    __nv_bfloat16 l3 = __float2bfloat16(v.w - __bfloat162float(h3));
    ushort4 ph = { __bfloat16_as_ushort(h0), __bfloat16_as_ushort(h1),
                   __bfloat16_as_ushort(h2), __bfloat16_as_ushort(h3) };
    ushort4 pl = { __bfloat16_as_ushort(l0), __bfloat16_as_ushort(l1),
                   __bfloat16_as_ushort(l2), __bfloat16_as_ushort(l3) };
    ((ushort4*)hi)[i] = ph;
    ((ushort4*)lo)[i] = pl;
}

__global__ __launch_bounds__(256)
void split32(const float* __restrict__ s, __nv_bfloat16* __restrict__ hi,
             __nv_bfloat16* __restrict__ lo)
{
    int i = blockIdx.x * blockDim.x + threadIdx.x;
    split4(((const float4*)s)[i], hi, lo, i);
}

// One launch splitting all five weight matrices.
__global__ __launch_bounds__(256)
void split_w(const float* __restrict__ Wq, const float* __restrict__ Wk,
             const float* __restrict__ Wv, const float* __restrict__ Wg,
             const float* __restrict__ Wo,
             __nv_bfloat16* __restrict__ wqh, __nv_bfloat16* __restrict__ wql,
             __nv_bfloat16* __restrict__ wkh, __nv_bfloat16* __restrict__ wkl,
             __nv_bfloat16* __restrict__ wvh, __nv_bfloat16* __restrict__ wvl,
             __nv_bfloat16* __restrict__ wgh, __nv_bfloat16* __restrict__ wgl,
             __nv_bfloat16* __restrict__ woh, __nv_bfloat16* __restrict__ wol)
{
    int b = blockIdx.x;
    const float* src; __nv_bfloat16 *hi, *lo;
    if      (b < 2048)  { src = Wq; hi = wqh; lo = wql; }
    else if (b < 4096)  { src = Wk; hi = wkh; lo = wkl; b -= 2048; }
    else if (b < 8192)  { src = Wv; hi = wvh; lo = wvl; b -= 4096; }
    else if (b < 12288) { src = Wg; hi = wgh; lo = wgl; b -= 8192; }
    else                { src = Wo; hi = woh; lo = wol; b -= 12288; }
    int i = b * 256 + threadIdx.x;
    split4(((const float4*)src)[i], hi, lo, i);
}

// ---------------------------------------------------------------------------
// Low-rank gate (fp32 SIMT — tiny)
// ---------------------------------------------------------------------------
__global__ void kg_gemm1(const float* __restrict__ x, const float* __restrict__ W,
                         float* __restrict__ t16)
{
    int idx = blockIdx.x * blockDim.x + threadIdx.x;   // 4096*16
    int m = idx >> 4, n = idx & 15;
    const float* xr = x + (size_t)m * DMODEL;
    const float* wr = W + (size_t)n * DMODEL;
    float acc = 0.f;
#pragma unroll 4
    for (int kk = 0; kk < DMODEL; kk += 4) {
        float4 a = *(const float4*)(xr + kk);
        float4 b = *(const float4*)(wr + kk);
        acc += a.x * b.x + a.y * b.y + a.z * b.z + a.w * b.w;
    }
    t16[idx] = acc;
}

__global__ void kg_gemm2(const float* __restrict__ t16, const float* __restrict__ W2,
                         const float* __restrict__ b2, float* __restrict__ kg)
{
    int idx = blockIdx.x * blockDim.x + threadIdx.x;   // 4096*1024
    int m = idx >> 10, n = idx & 1023;
    const float* tr = t16 + (size_t)m * 16;
    const float* wr = W2 + (size_t)n * 16;
    float acc = b2[n];
#pragma unroll
    for (int c = 0; c < 16; c++) acc = fmaf(tr[c], wr[c], acc);
    kg[idx] = acc;
}

// ---------------------------------------------------------------------------
// GLA recurrence. 256 blocks = B * H * 8 dv-chunks of 16; 128 threads.
// ~2 blocks/SM so barrier/shfl latency cross-hides between blocks.
// ---------------------------------------------------------------------------
#define TT 16
__global__ __launch_bounds__(128)
void gla_rec(const float* __restrict__ q, const float* __restrict__ k,
             const float* __restrict__ kg, const float* __restrict__ v,
             float* __restrict__ o)
{
    const int blk   = blockIdx.x;       // 256 = B * H * 8
    const int chunk = blk & 7;
    const int head  = (blk >> 3) & 15;
    const int b     = blk >> 7;
    const int j0    = chunk * 16;

    const int tid = threadIdx.x;
    const int j   = tid >> 3;           // 0..15
    const int ig  = tid & 7;            // 0..7

    __shared__ __align__(16) float qs[TT][DK];
    __shared__ __align__(16) float ks[TT][DK];
    __shared__ __align__(16) float es[TT][DK];
    __shared__ __align__(16) float vs[TT][16];

    const float* qb = q  + (size_t)b * SEQ * DQK    + head * DK;
    const float* kb = k  + (size_t)b * SEQ * DQK    + head * DK;
    const float* gb = kg + (size_t)b * SEQ * DQK    + head * DK;
    const float* vb = v  + (size_t)b * SEQ * DMODEL + head * DV + j0;
    float*       ob = o  + (size_t)b * SEQ * DMODEL + head * DV + j0;

    float S[8] = {0.f, 0.f, 0.f, 0.f, 0.f, 0.f, 0.f, 0.f};

    for (int t0 = 0; t0 < SEQ; t0 += TT) {
        // q/k/g: TT*64 floats = 256 float4 over 128 threads (2 each)
#pragma unroll
        for (int it = 0; it < 2; it++) {
            int idx = it * 128 + tid;
            int row = idx >> 4, c4 = idx & 15;
            size_t r4 = (size_t)(t0 + row) * (DQK / 4) + c4;
            float4 qv = ((const float4*)qb)[r4];
            float4 kv = ((const float4*)kb)[r4];
            float4 gv = ((const float4*)gb)[r4];
            *(float4*)&qs[row][c4 * 4] = qv;
            *(float4*)&ks[row][c4 * 4] = kv;
            float4 ev;
            float a0 = fminf(gv.x, 0.f) - log1pf(__expf(-fabsf(gv.x)));
            float a1 = fminf(gv.y, 0.f) - log1pf(__expf(-fabsf(gv.y)));
            float a2 = fminf(gv.z, 0.f) - log1pf(__expf(-fabsf(gv.z)));
            float a3 = fminf(gv.w, 0.f) - log1pf(__expf(-fabsf(gv.w)));
            ev.x = __expf(a0 * INV_NORM); ev.y = __expf(a1 * INV_NORM);
            ev.z = __expf(a2 * INV_NORM); ev.w = __expf(a3 * INV_NORM);
            *(float4*)&es[row][c4 * 4] = ev;
        }
        // v: TT*16 floats = 64 float4 (first 64 threads)
        if (tid < 64) {
            int row = tid >> 2, c4 = tid & 3;
            float4 vv = ((const float4*)vb)[(size_t)(t0 + row) * (DMODEL / 4) + c4];
            *(float4*)&vs[row][c4 * 4] = vv;
        }
        __syncthreads();

        for (int tt = 0; tt < TT; tt++) {
            float vj  = vs[tt][j];
            float acc = 0.f;
#pragma unroll
            for (int r = 0; r < 8; r++) {
                int i = ig * 8 + r;
                float s = fmaf(S[r], es[tt][i], ks[tt][i] * vj);
                S[r] = s;
                acc = fmaf(qs[tt][i], s, acc);
            }
            acc += __shfl_xor_sync(0xffffffffu, acc, 4);
            acc += __shfl_xor_sync(0xffffffffu, acc, 2);
            acc += __shfl_xor_sync(0xffffffffu, acc, 1);
            if (ig == 0) ob[(size_t)(t0 + tt) * DMODEL + j] = acc;
        }
        __syncthreads();
    }
}

// ---------------------------------------------------------------------------
// LayerNorm(dv=128, no affine) + SiLU gate, fused hi/lo bf16 split of z
// ---------------------------------------------------------------------------
__global__ __launch_bounds__(256)
void ln_gate(const float* __restrict__ o, const float* __restrict__ gp,
             __nv_bfloat16* __restrict__ zh, __nv_bfloat16* __restrict__ zl)
{
    int gw   = (blockIdx.x * blockDim.x + threadIdx.x) >> 5;   // row id, 65536 total
    int lane = threadIdx.x & 31;

    float4 ov = ((const float4*)(o + (size_t)gw * 128))[lane];
    float s = ov.x + ov.y + ov.z + ov.w;
#pragma unroll
    for (int d = 16; d > 0; d >>= 1) s += __shfl_xor_sync(0xffffffffu, s, d);
    float mu = s * (1.f / 128.f);

    float dx0 = ov.x - mu, dx1 = ov.y - mu, dx2 = ov.z - mu, dx3 = ov.w - mu;
    float vsum = dx0 * dx0 + dx1 * dx1 + dx2 * dx2 + dx3 * dx3;
#pragma unroll
    for (int d = 16; d > 0; d >>= 1) vsum += __shfl_xor_sync(0xffffffffu, vsum, d);
    float inv = rsqrtf(vsum * (1.f / 128.f) + 1e-5f);

    float4 gv = ((const float4*)(gp + (size_t)gw * 128))[lane];
    float4 z;
    z.x = (gv.x / (1.f + __expf(-gv.x))) * (dx0 * inv);
    z.y = (gv.y / (1.f + __expf(-gv.y))) * (dx1 * inv);
    z.z = (gv.z / (1.f + __expf(-gv.z))) * (dx2 * inv);
    z.w = (gv.w / (1.f + __expf(-gv.w))) * (dx3 * inv);
    split4(z, zh, zl, gw * 32 + lane);
}

// ---------------------------------------------------------------------------
extern "C" void kernel_launch(void* const* d_in, const int* in_sizes, int n_in,
                              void* d_out, int out_size)
{
    const float* x    = (const float*)d_in[0];
    const float* Wq   = (const float*)d_in[1];
    const float* Wk   = (const float*)d_in[2];
    const float* Wkg1 = (const float*)d_in[3];
    const float* Wkg2 = (const float*)d_in[4];
    const float* bkg2 = (const float*)d_in[5];
    const float* Wv   = (const float*)d_in[6];
    const float* Wg   = (const float*)d_in[7];
    const float* bg   = (const float*)d_in[8];
    const float* Wo   = (const float*)d_in[9];
    float* out = (float*)d_out;

    float *q, *k, *kg, *v, *gp, *o, *t16;
    cudaGetSymbolAddress((void**)&q,   g_q);
    cudaGetSymbolAddress((void**)&k,   g_k);
    cudaGetSymbolAddress((void**)&kg,  g_kg);
    cudaGetSymbolAddress((void**)&v,   g_v);
    cudaGetSymbolAddress((void**)&gp,  g_gp);
    cudaGetSymbolAddress((void**)&o,   g_o);
    cudaGetSymbolAddress((void**)&t16, g_t16);

    __nv_bfloat16 *xh, *xl, *zh, *zl;
    __nv_bfloat16 *wqh, *wql, *wkh, *wkl, *wvh, *wvl, *wgh, *wgl, *woh, *wol;
    cudaGetSymbolAddress((void**)&xh,  g_xh);  cudaGetSymbolAddress((void**)&xl,  g_xl);
    cudaGetSymbolAddress((void**)&zh,  g_zh);  cudaGetSymbolAddress((void**)&zl,  g_zl);
    cudaGetSymbolAddress((void**)&wqh, g_wqh); cudaGetSymbolAddress((void**)&wql, g_wql);
    cudaGetSymbolAddress((void**)&wkh, g_wkh); cudaGetSymbolAddress((void**)&wkl, g_wkl);
    cudaGetSymbolAddress((void**)&wvh, g_wvh); cudaGetSymbolAddress((void**)&wvl, g_wvl);
    cudaGetSymbolAddress((void**)&wgh, g_wgh); cudaGetSymbolAddress((void**)&wgl, g_wgl);
    cudaGetSymbolAddress((void**)&woh, g_woh); cudaGetSymbolAddress((void**)&wol, g_wol);

    cudaFuncSetAttribute(gemm3, cudaFuncAttributeMaxDynamicSharedMemorySize, GEMM_DSM);

    // hi/lo splits: 2 launches
    split32<<<(MTOK * DMODEL) / 1024, 256>>>(x, xh, xl);
    split_w<<<16384, 256>>>(Wq, Wk, Wv, Wg, Wo,
                            wqh, wql, wkh, wkl, wvh, wvl, wgh, wgl, woh, wol);

    dim3 blk(GEMM_THREADS);
    dim3 gQK(DQK / 256, MTOK / 128);      // 4 x 32
    dim3 gD (DMODEL / 256, MTOK / 128);   // 8 x 32

    gemm3<<<gQK, blk, GEMM_DSM>>>(xh, xl, wqh, wql, nullptr, q,  DQK,    DMODEL, 1.f);
    gemm3<<<gQK, blk, GEMM_DSM>>>(xh, xl, wkh, wkl, nullptr, k,  DQK,    DMODEL, SCALE_K);
    gemm3<<<gD,  blk, GEMM_DSM>>>(xh, xl, wvh, wvl, nullptr, v,  DMODEL, DMODEL, 1.f);
    gemm3<<<gD,  blk, GEMM_DSM>>>(xh, xl, wgh, wgl, bg,      gp, DMODEL, DMODEL, 1.f);

    kg_gemm1<<<(MTOK * 16) / 256, 256>>>(x, Wkg1, t16);
    kg_gemm2<<<(MTOK * DQK) / 256, 256>>>(t16, Wkg2, bkg2, kg);

    gla_rec<<<256, 128>>>(q, k, kg, v, o);

    ln_gate<<<(MTOK * NHEAD * 32) / 256, 256>>>(o, gp, zh, zl);

    gemm3<<<gD, blk, GEMM_DSM>>>(zh, zl, woh, wol, nullptr, out, DMODEL, DMODEL, 1.f);
}

// round 8
// speedup vs baseline: 1.2265x; 1.1688x over previous
#include <cuda_runtime.h>
#include <cuda_bf16.h>
#include <math.h>
#include <cstdint>

// ---------------------------------------------------------------------------
// Problem constants: B=2, L=2048, D=2048, H=16, dk=64, dv=128.  M = B*L = 4096.
// ---------------------------------------------------------------------------
#define MTOK 4096
#define DMODEL 2048
#define DQK 1024
#define NHEAD 16
#define DK 64
#define DV 128
#define SEQ 2048
#define SCALE_K 0.08838834764831845f   // 128^-0.5
#define INV_NORM 0.0625f               // 1/16

// tcgen05 only exists in the arch-specific (sm_103a) compilation pass.
#if defined(__CUDA_ARCH__) && (__CUDA_ARCH__ == 1030) && defined(__CUDA_ARCH_FEAT_SM103_ALL)
#define USE_TCGEN05 1
#else
#define USE_TCGEN05 0
#endif

// ---------------------------------------------------------------------------
// Scratch (device globals: no allocation allowed)
// ---------------------------------------------------------------------------
__device__ float g_q [MTOK * DQK];
__device__ float g_k [MTOK * DQK];
__device__ float g_kg[MTOK * DQK];
__device__ float g_v [MTOK * DMODEL];
__device__ float g_gp[MTOK * DMODEL];
__device__ float g_o [MTOK * DMODEL];

__device__ __nv_bfloat16 g_xh[MTOK * DMODEL],   g_xl[MTOK * DMODEL];
__device__ __nv_bfloat16 g_zh[MTOK * DMODEL],   g_zl[MTOK * DMODEL];
__device__ __nv_bfloat16 g_wqh[DQK * DMODEL],   g_wql[DQK * DMODEL];
__device__ __nv_bfloat16 g_wkh[DQK * DMODEL],   g_wkl[DQK * DMODEL];
__device__ __nv_bfloat16 g_weh[DQK * DMODEL],   g_wel[DQK * DMODEL];   // Wkg2@Wkg1
__device__ __nv_bfloat16 g_wvh[DMODEL * DMODEL], g_wvl[DMODEL * DMODEL];
__device__ __nv_bfloat16 g_wgh[DMODEL * DMODEL], g_wgl[DMODEL * DMODEL];
__device__ __nv_bfloat16 g_woh[DMODEL * DMODEL], g_wol[DMODEL * DMODEL];

// ---------------------------------------------------------------------------
// PTX helpers
// ---------------------------------------------------------------------------
__device__ __forceinline__ uint32_t smem_u32(const void* p) {
    uint32_t a;
    asm("{ .reg .u64 t; cvta.to.shared.u64 t, %1; cvt.u32.u64 %0, t; }" : "=r"(a) : "l"(p));
    return a;
}

#define SWZ(o) ((o) ^ (((o) >> 3) & 0x70))

#define CP_ASYNC16(dst, src) \
    asm volatile("cp.async.cg.shared.global [%0], [%1], 16;" :: "r"(dst), "l"(src))
// Arrive-on-complete of ALL prior cp.async by this thread; .noinc counts
// against the barrier's initialized expected-arrival count (pipeline idiom).
#define CP_ASYNC_MBAR_ARRIVE(mb) \
    asm volatile("cp.async.mbarrier.arrive.noinc.shared.b64 [%0];" :: "r"((uint32_t)(mb)) : "memory")
#define CP_ASYNC_COMMIT() \
    asm volatile("cp.async.commit_group;" ::: "memory")
#define CP_ASYNC_WAIT(n) \
    asm volatile("cp.async.wait_group %0;" :: "n"(n) : "memory")

#define MBARRIER_INIT(mb, cnt) \
    asm volatile("mbarrier.init.shared.b64 [%0], %1;" :: "r"((uint32_t)(mb)), "r"((uint32_t)(cnt)) : "memory")

#define MBARRIER_WAIT_PARITY(mb, par) do { \
    uint32_t _mb = (uint32_t)(mb); uint32_t _p = (uint32_t)(par); uint32_t _done; \
    asm volatile("{\n\t.reg .pred p;\n\t" \
        "mbarrier.try_wait.parity.acquire.cta.shared::cta.b64 p, [%1], %2;\n\t" \
        "selp.b32 %0, 1, 0, p;\n\t}" : "=r"(_done) : "r"(_mb), "r"(_p) : "memory"); \
    if (!_done) { \
        asm volatile("{\n\t.reg .pred P1;\n\t" \
            "WL_%=:\n\t" \
            "mbarrier.try_wait.parity.acquire.cta.shared::cta.b64 P1, [%0], %1, 0x989680;\n\t" \
            "@P1 bra.uni WD_%=;\n\t" \
            "bra.uni WL_%=;\n\t" \
            "WD_%=:\n\t}" :: "r"(_mb), "r"(_p) : "memory"); \
    } \
} while (0)

#if USE_TCGEN05
__device__ __forceinline__ uint32_t elect_one_pred() {
    uint32_t pred;
    asm volatile("{\n\t.reg .pred p;\n\telect.sync _|p, 0xFFFFFFFF;\n\t"
                 "selp.b32 %0, 1, 0, p;\n\t}" : "=r"(pred));
    return pred;
}

#define TCGEN05_ALLOC(smem_res, ncols) \
    asm volatile("tcgen05.alloc.cta_group::1.sync.aligned.shared::cta.b32 [%0], %1;" \
                 :: "r"((uint32_t)(smem_res)), "r"((uint32_t)(ncols)) : "memory")
#define TCGEN05_DEALLOC(tm, ncols) \
    asm volatile("tcgen05.dealloc.cta_group::1.sync.aligned.b32 %0, %1;" :: "r"(tm), "r"((uint32_t)(ncols)))
#define TCGEN05_RELINQ() \
    asm volatile("tcgen05.relinquish_alloc_permit.cta_group::1.sync.aligned;")
#define TCGEN05_COMMIT(mb) \
    asm volatile("tcgen05.commit.cta_group::1.mbarrier::arrive::one.shared::cluster.b64 [%0];" \
                 :: "r"((uint32_t)(mb)) : "memory")
#define TCGEN05_FENCE_AFTER() \
    asm volatile("tcgen05.fence::after_thread_sync;" ::: "memory")
#define TCGEN05_WAIT_LD() \
    asm volatile("tcgen05.wait::ld.sync.aligned;" ::: "memory")
#define FENCE_PROXY_ASYNC() \
    asm volatile("fence.proxy.async.shared::cta;" ::: "memory")

#define TCGEN05_LD_X32(r, tm) \
    asm volatile("tcgen05.ld.sync.aligned.32x32b.x32.b32 " \
        "{%0, %1, %2, %3, %4, %5, %6, %7, %8, %9, %10, %11, %12, %13, %14, %15, " \
        " %16, %17, %18, %19, %20, %21, %22, %23, %24, %25, %26, %27, %28, %29, %30, %31}, [%32];" \
        : "=r"((r)[0]),  "=r"((r)[1]),  "=r"((r)[2]),  "=r"((r)[3]), \
          "=r"((r)[4]),  "=r"((r)[5]),  "=r"((r)[6]),  "=r"((r)[7]), \
          "=r"((r)[8]),  "=r"((r)[9]),  "=r"((r)[10]), "=r"((r)[11]), \
          "=r"((r)[12]), "=r"((r)[13]), "=r"((r)[14]), "=r"((r)[15]), \
          "=r"((r)[16]), "=r"((r)[17]), "=r"((r)[18]), "=r"((r)[19]), \
          "=r"((r)[20]), "=r"((r)[21]), "=r"((r)[22]), "=r"((r)[23]), \
          "=r"((r)[24]), "=r"((r)[25]), "=r"((r)[26]), "=r"((r)[27]), \
          "=r"((r)[28]), "=r"((r)[29]), "=r"((r)[30]), "=r"((r)[31]) \
        : "r"(tm))

// K-major SW128 descriptor: layout=2 (SW128), version=1, SBO=64, LBO=1
static constexpr uint64_t DESC_BASE_SW128 =
    (uint64_t(2) << 61) | (uint64_t(1) << 46) | (uint64_t(64) << 32) | (uint64_t(1) << 16);
#define MAKE_DESC(addr) (DESC_BASE_SW128 | ((uint64_t)((addr) >> 4) & 0x3FFF))

__device__ __forceinline__ void mma_f16_ss(uint32_t d, uint64_t ad, uint64_t bd,
                                           uint32_t idesc, uint32_t en) {
    asm volatile("{\n\t.reg .pred p;\n\tsetp.ne.u32 p, %5, 0;\n\t"
        "tcgen05.mma.cta_group::1.kind::f16 [%0], %1, %2, %3, {%4, %4, %4, %4}, p;\n\t}"
        :: "r"(d), "l"(ad), "l"(bd), "r"(idesc), "r"(0u), "r"(en) : "memory");
}
#else
// HMMA fallback primitive: m16n8k16 row.col bf16 -> f32
__device__ __forceinline__ void mma16816(float* d, const uint32_t* a, const uint32_t* b) {
    asm volatile("mma.sync.aligned.m16n8k16.row.col.f32.bf16.bf16.f32 "
        "{%0,%1,%2,%3}, {%4,%5,%6,%7}, {%8,%9}, {%0,%1,%2,%3};"
        : "+f"(d[0]), "+f"(d[1]), "+f"(d[2]), "+f"(d[3])
        : "r"(a[0]), "r"(a[1]), "r"(a[2]), "r"(a[3]), "r"(b[0]), "r"(b[1]));
}
#endif

// ---------------------------------------------------------------------------
// bf16x3 GEMM:  C[M,N] = alpha * (A @ B^T) (+ bias), split hi/lo operands.
// Tile 128x256 (two N=128 MMA halves), K-chunk 64, WARP-SPECIALIZED:
//   threads 0..255  = loaders (cp.async + noinc mbarrier arrive)
//   warp 8 (256..287) = MMA warp (full-wait -> 24 MMA -> commit -> empty)
// ---------------------------------------------------------------------------
#define BUFB 98304
#define GEMM_DSM (2 * BUFB + 1024)
#define GEMM_THREADS 288

__global__ __launch_bounds__(GEMM_THREADS) __cluster_dims__(1, 1, 1)
void gemm3(const __nv_bfloat16* __restrict__ Ah, const __nv_bfloat16* __restrict__ Al,
           const __nv_bfloat16* __restrict__ Bh, const __nv_bfloat16* __restrict__ Bl,
           const float* __restrict__ bias, float* __restrict__ C,
           int N, int K, float alpha)
{
    extern __shared__ char dsm[];

    const int tid = threadIdx.x;
    const int bm = blockIdx.y * 128;
    const int bn = blockIdx.x * 256;

    const uint32_t raw = smem_u32(dsm);
    const uint32_t sbase = (raw + 1023u) & ~1023u;
    char* sgen = dsm + (sbase - raw);

    const int NC = K / 64;

#if USE_TCGEN05
    __shared__ uint32_t s_tmem;
    __shared__ __align__(16) uint64_t s_full[2];
    __shared__ __align__(16) uint64_t s_empty[2];
    const uint32_t full0  = smem_u32(&s_full[0]),  full1  = smem_u32(&s_full[1]);
    const uint32_t empty0 = smem_u32(&s_empty[0]), empty1 = smem_u32(&s_empty[1]);

    if (tid < 32) { TCGEN05_ALLOC(smem_u32(&s_tmem), 256); TCGEN05_RELINQ(); }
    if (tid == 0) {
        MBARRIER_INIT(full0, 256);  MBARRIER_INIT(full1, 256);
        MBARRIER_INIT(empty0, 1);   MBARRIER_INIT(empty1, 1);
    }
    __syncthreads();
    const uint32_t tmem = s_tmem;

    if (tid < 256) {
        // ---------------- loader role ----------------
        const int lr  = tid >> 3;          // 0..31 base row
        const int seg = tid & 7;           // 16B segment within 128B row
        for (int c = 0; c < NC; c++) {
            if (c >= 2)
                MBARRIER_WAIT_PARITY((c & 1) ? empty1 : empty0, ((c - 2) >> 1) & 1);
            const uint32_t bb = sbase + (c & 1) * BUFB;
            const int k0 = c * 64;
#pragma unroll
            for (int t2 = 0; t2 < 2; t2++) {               // Ah, Al (128 rows)
                const __nv_bfloat16* basep = t2 ? Al : Ah;
                uint32_t tb = bb + t2 * 16384;
#pragma unroll
                for (int ii = 0; ii < 4; ii++) {
                    int r = lr + ii * 32;
                    const void* src = basep + (size_t)(bm + r) * K + k0 + seg * 8;
                    CP_ASYNC16(tb + SWZ((uint32_t)(r * 128 + seg * 16)), src);
                }
            }
#pragma unroll
            for (int t2 = 0; t2 < 2; t2++) {               // Bh, Bl (256 rows)
                const __nv_bfloat16* basep = t2 ? Bl : Bh;
                uint32_t tb = bb + 32768 + t2 * 32768;
#pragma unroll
                for (int ii = 0; ii < 8; ii++) {
                    int r = lr + ii * 32;
                    const void* src = basep + (size_t)(bn + r) * K + k0 + seg * 8;
                    CP_ASYNC16(tb + SWZ((uint32_t)(r * 128 + seg * 16)), src);
                }
            }
            CP_ASYNC_MBAR_ARRIVE((c & 1) ? full1 : full0);
        }
    } else if (elect_one_pred()) {
        // ---------------- MMA role (single elected thread of warp 8) --------
        const uint32_t IDESC = (1u << 4) | (1u << 7) | (1u << 10) | (16u << 17) | (8u << 24);
        for (int c = 0; c < NC; c++) {
            MBARRIER_WAIT_PARITY((c & 1) ? full1 : full0, (c >> 1) & 1);
            FENCE_PROXY_ASYNC();           // generic (cp.async) -> async proxy
            const uint32_t ab = sbase + (c & 1) * BUFB;
            const uint64_t dAh  = MAKE_DESC(ab);
            const uint64_t dAl  = MAKE_DESC(ab + 16384);
            const uint64_t dBh0 = MAKE_DESC(ab + 32768);
            const uint64_t dBh1 = MAKE_DESC(ab + 32768 + 16384);
            const uint64_t dBl0 = MAKE_DESC(ab + 65536);
            const uint64_t dBl1 = MAKE_DESC(ab + 65536 + 16384);
            const uint32_t en0 = (c > 0);
#pragma unroll
            for (int ks = 0; ks < 4; ks++)
                mma_f16_ss(tmem,       dAh + ks * 2, dBh0 + ks * 2, IDESC, en0 || (ks > 0));
#pragma unroll
            for (int ks = 0; ks < 4; ks++)
                mma_f16_ss(tmem + 128, dAh + ks * 2, dBh1 + ks * 2, IDESC, en0 || (ks > 0));
#pragma unroll
            for (int ks = 0; ks < 4; ks++) {
                mma_f16_ss(tmem,       dAh + ks * 2, dBl0 + ks * 2, IDESC, 1u);
                mma_f16_ss(tmem + 128, dAh + ks * 2, dBl1 + ks * 2, IDESC, 1u);
                mma_f16_ss(tmem,       dAl + ks * 2, dBh0 + ks * 2, IDESC, 1u);
                mma_f16_ss(tmem + 128, dAl + ks * 2, dBh1 + ks * 2, IDESC, 1u);
            }
            TCGEN05_COMMIT((c & 1) ? empty1 : empty0);
        }
    }

    __syncthreads();
    // final MMA chunk NC-1: completion #((NC-1)>>1) on empty[(NC-1)&1]
    MBARRIER_WAIT_PARITY(((NC - 1) & 1) ? empty1 : empty0, ((NC - 1) >> 1) & 1);
    TCGEN05_FENCE_AFTER();
    __syncthreads();

    // epilogue: TMEM -> regs -> padded SMEM stage -> coalesced STG (8 slabs)
    float* stage = (float*)sgen;
    for (int slab = 0; slab < 8; slab++) {
        if (tid < 128) {
            uint32_t regs[32];
            TCGEN05_LD_X32(regs, tmem + slab * 32);
            TCGEN05_WAIT_LD();
#pragma unroll
            for (int cc = 0; cc < 32; cc++) stage[tid * 33 + cc] = __uint_as_float(regs[cc]);
        }
        __syncthreads();
        for (int e = tid; e < 4096; e += GEMM_THREADS) {
            int row = e >> 5, col = e & 31;
            float vv = stage[row * 33 + col] * alpha;
            if (bias) vv += bias[bn + slab * 32 + col];
            C[(size_t)(bm + row) * N + bn + slab * 32 + col] = vv;
        }
        __syncthreads();
    }
    if (tid < 32) TCGEN05_DEALLOC(tmem, 256);

#else  // ------------------- HMMA mma.sync fallback ------------------------
    const int warp = tid >> 5;
    const int lane = tid & 31;
    if (warp < 8) {
        const int wm = (warp & 3) * 32;
        const int wn = (warp >> 2) * 64;
        const int lg = lane >> 2;
        const int lt = lane & 3;
        const int lr  = tid >> 3;
        const int seg = tid & 7;

        auto load_chunk = [&](int c) {
            uint32_t bb = sbase + (c & 1) * BUFB;
            const int k0 = c * 64;
#pragma unroll
            for (int t2 = 0; t2 < 2; t2++) {
                const __nv_bfloat16* basep = t2 ? Al : Ah;
                uint32_t tb = bb + t2 * 16384;
#pragma unroll
                for (int ii = 0; ii < 4; ii++) {
                    int r = lr + ii * 32;
                    const void* src = basep + (size_t)(bm + r) * K + k0 + seg * 8;
                    CP_ASYNC16(tb + SWZ((uint32_t)(r * 128 + seg * 16)), src);
                }
            }
#pragma unroll
            for (int t2 = 0; t2 < 2; t2++) {
                const __nv_bfloat16* basep = t2 ? Bl : Bh;
                uint32_t tb = bb + 32768 + t2 * 32768;
#pragma unroll
                for (int ii = 0; ii < 8; ii++) {
                    int r = lr + ii * 32;
                    const void* src = basep + (size_t)(bn + r) * K + k0 + seg * 8;
                    CP_ASYNC16(tb + SWZ((uint32_t)(r * 128 + seg * 16)), src);
                }
            }
            CP_ASYNC_COMMIT();
        };

        for (int nh = 0; nh < 2; nh++) {
            float acc[2][8][4];
#pragma unroll
            for (int mt = 0; mt < 2; mt++)
#pragma unroll
                for (int nt = 0; nt < 8; nt++)
#pragma unroll
                    for (int r = 0; r < 4; r++) acc[mt][nt][r] = 0.f;

            load_chunk(0);
            for (int c = 0; c < NC; c++) {
                if (c + 1 < NC) { load_chunk(c + 1); CP_ASYNC_WAIT(1); }
                else            { CP_ASYNC_WAIT(0); }
                asm volatile("bar.sync 1, 256;" ::: "memory");

                char* bb = sgen + (c & 1) * BUFB;
                char* tAh = bb, *tAl = bb + 16384;
                char* tBh = bb + 32768 + nh * 16384, *tBl = bb + 65536 + nh * 16384;
#pragma unroll
                for (int kk = 0; kk < 64; kk += 16) {
                    const uint32_t kbase = (kk + lt * 2) * 2;
                    uint32_t bh[8][2], bl[8][2];
#pragma unroll
                    for (int nt = 0; nt < 8; nt++) {
                        uint32_t off = (uint32_t)((wn + nt * 8 + lg) * 128) + kbase;
                        bh[nt][0] = *(const uint32_t*)(tBh + SWZ(off));
                        bh[nt][1] = *(const uint32_t*)(tBh + SWZ(off + 16));
                        bl[nt][0] = *(const uint32_t*)(tBl + SWZ(off));
                        bl[nt][1] = *(const uint32_t*)(tBl + SWZ(off + 16));
                    }
#pragma unroll
                    for (int mt = 0; mt < 2; mt++) {
                        uint32_t o0 = (uint32_t)((wm + mt * 16 + lg) * 128) + kbase;
                        uint32_t o8 = o0 + 8 * 128;
                        uint32_t ah[4] = {
                            *(const uint32_t*)(tAh + SWZ(o0)),      *(const uint32_t*)(tAh + SWZ(o8)),
                            *(const uint32_t*)(tAh + SWZ(o0 + 16)), *(const uint32_t*)(tAh + SWZ(o8 + 16)) };
                        uint32_t al[4] = {
                            *(const uint32_t*)(tAl + SWZ(o0)),      *(const uint32_t*)(tAl + SWZ(o8)),
                            *(const uint32_t*)(tAl + SWZ(o0 + 16)), *(const uint32_t*)(tAl + SWZ(o8 + 16)) };
#pragma unroll
                        for (int nt = 0; nt < 8; nt++) mma16816(acc[mt][nt], ah, bh[nt]);
#pragma unroll
                        for (int nt = 0; nt < 8; nt++) mma16816(acc[mt][nt], ah, bl[nt]);
#pragma unroll
                        for (int nt = 0; nt < 8; nt++) mma16816(acc[mt][nt], al, bh[nt]);
                    }
                }
                asm volatile("bar.sync 1, 256;" ::: "memory");
            }
#pragma unroll
            for (int mt = 0; mt < 2; mt++) {
#pragma unroll
                for (int nt = 0; nt < 8; nt++) {
                    int row = bm + wm + mt * 16 + lg;
                    int col = bn + nh * 128 + wn + nt * 8 + lt * 2;
                    float b0 = bias ? bias[col]     : 0.f;
                    float b1 = bias ? bias[col + 1] : 0.f;
                    float2 v0 = { acc[mt][nt][0] * alpha + b0, acc[mt][nt][1] * alpha + b1 };
                    float2 v1 = { acc[mt][nt][2] * alpha + b0, acc[mt][nt][3] * alpha + b1 };
                    *(float2*)(C + (size_t)row * N + col)       = v0;
                    *(float2*)(C + (size_t)(row + 8) * N + col) = v1;
                }
            }
            asm volatile("bar.sync 1, 256;" ::: "memory");
        }
    }
#endif
}

// ---------------------------------------------------------------------------
// fp32 -> (hi, lo) bf16 split, vectorized by 4
// ---------------------------------------------------------------------------
__device__ __forceinline__ void split4(const float4 v,
                                       __nv_bfloat16* hi, __nv_bfloat16* lo, int i)
{
    __nv_bfloat16 h0 = __float2bfloat16(v.x), h1 = __float2bfloat16(v.y);
    __nv_bfloat16 h2 = __float2bfloat16(v.z), h3 = __float2bfloat16(v.w);
    __nv_bfloat16 l0 = __float2bfloat16(v.x - __bfloat162float(h0));
    __nv_bfloat16 l1 = __float2bfloat16(v.y - __bfloat162float(h1));
    __nv_bfloat16 l2 = __float2bfloat16(v.z - __bfloat162float(h2));
    __nv_bfloat16 l3 = __float2bfloat16(v.w - __bfloat162float(h3));
    ushort4 ph = { __bfloat16_as_ushort(h0), __bfloat16_as_ushort(h1),
                   __bfloat16_as_ushort(h2), __bfloat16_as_ushort(h3) };
    ushort4 pl = { __bfloat16_as_ushort(l0), __bfloat16_as_ushort(l1),
                   __bfloat16_as_ushort(l2), __bfloat16_as_ushort(l3) };
    ((ushort4*)hi)[i] = ph;
    ((ushort4*)lo)[i] = pl;
}

__global__ __launch_bounds__(256)
void split32(const float* __restrict__ s, __nv_bfloat16* __restrict__ hi,
             __nv_bfloat16* __restrict__ lo)
{
    int i = blockIdx.x * blockDim.x + threadIdx.x;
    split4(((const float4*)s)[i], hi, lo, i);
}

// One launch splitting all five weight matrices.
__global__ __launch_bounds__(256)
void split_w(const float* __restrict__ Wq, const float* __restrict__ Wk,
             const float* __restrict__ Wv, const float* __restrict__ Wg,
             const float* __restrict__ Wo,
             __nv_bfloat16* __restrict__ wqh, __nv_bfloat16* __restrict__ wql,
             __nv_bfloat16* __restrict__ wkh, __nv_bfloat16* __restrict__ wkl,
             __nv_bfloat16* __restrict__ wvh, __nv_bfloat16* __restrict__ wvl,
             __nv_bfloat16* __restrict__ wgh, __nv_bfloat16* __restrict__ wgl,
             __nv_bfloat16* __restrict__ woh, __nv_bfloat16* __restrict__ wol)
{
    int b = blockIdx.x;
    const float* src; __nv_bfloat16 *hi, *lo;
    if      (b < 2048)  { src = Wq; hi = wqh; lo = wql; }
    else if (b < 4096)  { src = Wk; hi = wkh; lo = wkl; b -= 2048; }
    else if (b < 8192)  { src = Wv; hi = wvh; lo = wvl; b -= 4096; }
    else if (b < 12288) { src = Wg; hi = wgh; lo = wgl; b -= 8192; }
    else                { src = Wo; hi = woh; lo = wol; b -= 12288; }
    int i = b * 256 + threadIdx.x;
    split4(((const float4*)src)[i], hi, lo, i);
}

// ---------------------------------------------------------------------------
// W_eff = Wkg2 @ Wkg1  ([1024,16] @ [16,2048] -> [1024,2048]), fused hi/lo
// split.  kg = x @ W_eff^T + bkg2 then runs on the tcgen05 GEMM — replaces
// the LSU-bound kg_gemm1/kg_gemm2 pair (~600us) with ~5us + one gemm3.
// Grid (16, 4): blockIdx.x = 128-col d-chunk, blockIdx.y = 256-row n-chunk.
// ---------------------------------------------------------------------------
__global__ __launch_bounds__(256)
void weff_split(const float* __restrict__ W1,   // Wkg1 [16, 2048]
                const float* __restrict__ W2,   // Wkg2 [1024, 16]
                __nv_bfloat16* __restrict__ weh, __nv_bfloat16* __restrict__ wel)
{
    __shared__ __align__(16) float s1[16][128];
    const int tid = threadIdx.x;
    const int d0  = blockIdx.x * 128;
    const int n0  = blockIdx.y * 256;

    // stage Wkg1[:, d0:d0+128]: 512 float4
#pragma unroll
    for (int it = 0; it < 2; it++) {
        int i = it * 256 + tid;
        int r = i >> 5, c4 = i & 31;
        *(float4*)&s1[r][c4 * 4] = *(const float4*)(W1 + r * DMODEL + d0 + c4 * 4);
    }
    __syncthreads();

    const int d4 = tid & 31;       // float4 col within chunk
    const int nb = tid >> 5;       // 0..7
    for (int n = n0 + nb; n < n0 + 256; n += 8) {
        const float4 w2a = *(const float4*)(W2 + n * 16);
        const float4 w2b = *(const float4*)(W2 + n * 16 + 4);
        const float4 w2c = *(const float4*)(W2 + n * 16 + 8);
        const float4 w2d = *(const float4*)(W2 + n * 16 + 12);
        float w2[16] = { w2a.x, w2a.y, w2a.z, w2a.w, w2b.x, w2b.y, w2b.z, w2b.w,
                         w2c.x, w2c.y, w2c.z, w2c.w, w2d.x, w2d.y, w2d.z, w2d.w };
        float4 acc = {0.f, 0.f, 0.f, 0.f};
#pragma unroll
        for (int r = 0; r < 16; r++) {
            float4 v = *(const float4*)&s1[r][d4 * 4];
            acc.x = fmaf(w2[r], v.x, acc.x);
            acc.y = fmaf(w2[r], v.y, acc.y);
            acc.z = fmaf(w2[r], v.z, acc.z);
            acc.w = fmaf(w2[r], v.w, acc.w);
        }
        split4(acc, weh, wel, n * (DMODEL / 4) + (d0 >> 2) + d4);
    }
}

// ---------------------------------------------------------------------------
// GLA recurrence. 256 blocks = B * H * 8 dv-chunks of 16; 128 threads.
// ---------------------------------------------------------------------------
#define TT 16
__global__ __launch_bounds__(128)
void gla_rec(const float* __restrict__ q, const float* __restrict__ k,
             const float* __restrict__ kg, const float* __restrict__ v,
             float* __restrict__ o)
{
    const int blk   = blockIdx.x;       // 256 = B * H * 8
    const int chunk = blk & 7;
    const int head  = (blk >> 3) & 15;
    const int b     = blk >> 7;
    const int j0    = chunk * 16;

    const int tid = threadIdx.x;
    const int j   = tid >> 3;           // 0..15
    const int ig  = tid & 7;            // 0..7

    __shared__ __align__(16) float qs[TT][DK];
    __shared__ __align__(16) float ks[TT][DK];
    __shared__ __align__(16) float es[TT][DK];
    __shared__ __align__(16) float vs[TT][16];

    const float* qb = q  + (size_t)b * SEQ * DQK    + head * DK;
    const float* kb = k  + (size_t)b * SEQ * DQK    + head * DK;
    const float* gb = kg + (size_t)b * SEQ * DQK    + head * DK;
    const float* vb = v  + (size_t)b * SEQ * DMODEL + head * DV + j0;
    float*       ob = o  + (size_t)b * SEQ * DMODEL + head * DV + j0;

    float S[8] = {0.f, 0.f, 0.f, 0.f, 0.f, 0.f, 0.f, 0.f};

    for (int t0 = 0; t0 < SEQ; t0 += TT) {
        // q/k/g: TT*64 floats = 256 float4 over 128 threads (2 each)
#pragma unroll
        for (int it = 0; it < 2; it++) {
            int idx = it * 128 + tid;
            int row = idx >> 4, c4 = idx & 15;
            size_t r4 = (size_t)(t0 + row) * (DQK / 4) + c4;
            float4 qv = ((const float4*)qb)[r4];
            float4 kv = ((const float4*)kb)[r4];
            float4 gv = ((const float4*)gb)[r4];
            *(float4*)&qs[row][c4 * 4] = qv;
            *(float4*)&ks[row][c4 * 4] = kv;
            float4 ev;
            float a0 = fminf(gv.x, 0.f) - log1pf(__expf(-fabsf(gv.x)));
            float a1 = fminf(gv.y, 0.f) - log1pf(__expf(-fabsf(gv.y)));
            float a2 = fminf(gv.z, 0.f) - log1pf(__expf(-fabsf(gv.z)));
            float a3 = fminf(gv.w, 0.f) - log1pf(__expf(-fabsf(gv.w)));
            ev.x = __expf(a0 * INV_NORM); ev.y = __expf(a1 * INV_NORM);
            ev.z = __expf(a2 * INV_NORM); ev.w = __expf(a3 * INV_NORM);
            *(float4*)&es[row][c4 * 4] = ev;
        }
        // v: TT*16 floats = 64 float4 (first 64 threads)
        if (tid < 64) {
            int row = tid >> 2, c4 = tid & 3;
            float4 vv = ((const float4*)vb)[(size_t)(t0 + row) * (DMODEL / 4) + c4];
            *(float4*)&vs[row][c4 * 4] = vv;
        }
        __syncthreads();

        for (int tt = 0; tt < TT; tt++) {
            float vj  = vs[tt][j];
            float acc = 0.f;
#pragma unroll
            for (int r = 0; r < 8; r++) {
                int i = ig * 8 + r;
                float s = fmaf(S[r], es[tt][i], ks[tt][i] * vj);
                S[r] = s;
                acc = fmaf(qs[tt][i], s, acc);
            }
            acc += __shfl_xor_sync(0xffffffffu, acc, 4);
            acc += __shfl_xor_sync(0xffffffffu, acc, 2);
            acc += __shfl_xor_sync(0xffffffffu, acc, 1);
            if (ig == 0) ob[(size_t)(t0 + tt) * DMODEL + j] = acc;
        }
        __syncthreads();
    }
}

// ---------------------------------------------------------------------------
// LayerNorm(dv=128, no affine) + SiLU gate, fused hi/lo bf16 split of z
// ---------------------------------------------------------------------------
__global__ __launch_bounds__(256)
void ln_gate(const float* __restrict__ o, const float* __restrict__ gp,
             __nv_bfloat16* __restrict__ zh, __nv_bfloat16* __restrict__ zl)
{
    int gw   = (blockIdx.x * blockDim.x + threadIdx.x) >> 5;   // row id, 65536 total
    int lane = threadIdx.x & 31;

    float4 ov = ((const float4*)(o + (size_t)gw * 128))[lane];
    float s = ov.x + ov.y + ov.z + ov.w;
#pragma unroll
    for (int d = 16; d > 0; d >>= 1) s += __shfl_xor_sync(0xffffffffu, s, d);
    float mu = s * (1.f / 128.f);

    float dx0 = ov.x - mu, dx1 = ov.y - mu, dx2 = ov.z - mu, dx3 = ov.w - mu;
    float vsum = dx0 * dx0 + dx1 * dx1 + dx2 * dx2 + dx3 * dx3;
#pragma unroll
    for (int d = 16; d > 0; d >>= 1) vsum += __shfl_xor_sync(0xffffffffu, vsum, d);
    float inv = rsqrtf(vsum * (1.f / 128.f) + 1e-5f);

    float4 gv = ((const float4*)(gp + (size_t)gw * 128))[lane];
    float4 z;
    z.x = (gv.x / (1.f + __expf(-gv.x))) * (dx0 * inv);
    z.y = (gv.y / (1.f + __expf(-gv.y))) * (dx1 * inv);
    z.z = (gv.z / (1.f + __expf(-gv.z))) * (dx2 * inv);
    z.w = (gv.w / (1.f + __expf(-gv.w))) * (dx3 * inv);
    split4(z, zh, zl, gw * 32 + lane);
}

// ---------------------------------------------------------------------------
extern "C" void kernel_launch(void* const* d_in, const int* in_sizes, int n_in,
                              void* d_out, int out_size)
{
    const float* x    = (const float*)d_in[0];
    const float* Wq   = (const float*)d_in[1];
    const float* Wk   = (const float*)d_in[2];
    const float* Wkg1 = (const float*)d_in[3];
    const float* Wkg2 = (const float*)d_in[4];
    const float* bkg2 = (const float*)d_in[5];
    const float* Wv   = (const float*)d_in[6];
    const float* Wg   = (const float*)d_in[7];
    const float* bg   = (const float*)d_in[8];
    const float* Wo   = (const float*)d_in[9];
    float* out = (float*)d_out;

    float *q, *k, *kg, *v, *gp, *o;
    cudaGetSymbolAddress((void**)&q,   g_q);
    cudaGetSymbolAddress((void**)&k,   g_k);
    cudaGetSymbolAddress((void**)&kg,  g_kg);
    cudaGetSymbolAddress((void**)&v,   g_v);
    cudaGetSymbolAddress((void**)&gp,  g_gp);
    cudaGetSymbolAddress((void**)&o,   g_o);

    __nv_bfloat16 *xh, *xl, *zh, *zl;
    __nv_bfloat16 *wqh, *wql, *wkh, *wkl, *weh, *wel;
    __nv_bfloat16 *wvh, *wvl, *wgh, *wgl, *woh, *wol;
    cudaGetSymbolAddress((void**)&xh,  g_xh);  cudaGetSymbolAddress((void**)&xl,  g_xl);
    cudaGetSymbolAddress((void**)&zh,  g_zh);  cudaGetSymbolAddress((void**)&zl,  g_zl);
    cudaGetSymbolAddress((void**)&wqh, g_wqh); cudaGetSymbolAddress((void**)&wql, g_wql);
    cudaGetSymbolAddress((void**)&wkh, g_wkh); cudaGetSymbolAddress((void**)&wkl, g_wkl);
    cudaGetSymbolAddress((void**)&weh, g_weh); cudaGetSymbolAddress((void**)&wel, g_wel);
    cudaGetSymbolAddress((void**)&wvh, g_wvh); cudaGetSymbolAddress((void**)&wvl, g_wvl);
    cudaGetSymbolAddress((void**)&wgh, g_wgh); cudaGetSymbolAddress((void**)&wgl, g_wgl);
    cudaGetSymbolAddress((void**)&woh, g_woh); cudaGetSymbolAddress((void**)&wol, g_wol);

    cudaFuncSetAttribute(gemm3, cudaFuncAttributeMaxDynamicSharedMemorySize, GEMM_DSM);

    // splits + fused low-rank weight product
    split32<<<(MTOK * DMODEL) / 1024, 256>>>(x, xh, xl);
    split_w<<<16384, 256>>>(Wq, Wk, Wv, Wg, Wo,
                            wqh, wql, wkh, wkl, wvh, wvl, wgh, wgl, woh, wol);
    weff_split<<<dim3(16, 4), 256>>>(Wkg1, Wkg2, weh, wel);

    dim3 blk(GEMM_THREADS);
    dim3 gQK(DQK / 256, MTOK / 128);      // 4 x 32
    dim3 gD (DMODEL / 256, MTOK / 128);   // 8 x 32

    gemm3<<<gQK, blk, GEMM_DSM>>>(xh, xl, wqh, wql, nullptr, q,  DQK,    DMODEL, 1.f);
    gemm3<<<gQK, blk, GEMM_DSM>>>(xh, xl, wkh, wkl, nullptr, k,  DQK,    DMODEL, SCALE_K);
    gemm3<<<gQK, blk, GEMM_DSM>>>(xh, xl, weh, wel, bkg2,    kg, DQK,    DMODEL, 1.f);
    gemm3<<<gD,  blk, GEMM_DSM>>>(xh, xl, wvh, wvl, nullptr, v,  DMODEL, DMODEL, 1.f);
    gemm3<<<gD,  blk, GEMM_DSM>>>(xh, xl, wgh, wgl, bg,      gp, DMODEL, DMODEL, 1.f);

    gla_rec<<<256, 128>>>(q, k, kg, v, o);

    ln_gate<<<(MTOK * NHEAD * 32) / 256, 256>>>(o, gp, zh, zl);

    gemm3<<<gD, blk, GEMM_DSM>>>(zh, zl, woh, wol, nullptr, out, DMODEL, DMODEL, 1.f);
}